// round 1
// baseline (speedup 1.0000x reference)
#include <cuda_runtime.h>
#include <cuda_bf16.h>
#include <math.h>

#define NN 50000
#define EE 800000
#define ETOT (EE + NN)

// ---------------- scratch (no allocations allowed) ----------------
__device__ float    g_xh  [NN * 188];   // lin output (max width 188)
__device__ float    g_out [NN * 188];   // GAT aggregation accumulator
__device__ float    g_x1  [NN * 128];   // layer0 output
__device__ float    g_x2  [NN * 128];   // layer1 output
__device__ float    g_skip[NN * 128];   // skip GEMM output (max width 128)
__device__ float    g_asrc[NN * 4];
__device__ float    g_adst[NN * 4];
__device__ unsigned g_m   [NN * 4];     // segment max (monotone uint keys)
__device__ float    g_s   [NN * 4];     // segment sum of exp

// ---------------- helpers ----------------
__device__ __forceinline__ unsigned fkey(float f) {
    unsigned b = __float_as_uint(f);
    return (b & 0x80000000u) ? ~b : (b | 0x80000000u);
}
__device__ __forceinline__ float funkey(unsigned k) {
    return __uint_as_float((k & 0x80000000u) ? (k ^ 0x80000000u) : ~k);
}
__device__ __forceinline__ float lrelu(float e) {
    return fmaxf(e, 0.2f * e);
}
__device__ __forceinline__ void red4(float* p, float4 v) {
    asm volatile("red.global.add.v4.f32 [%0], {%1,%2,%3,%4};"
                 :: "l"(p), "f"(v.x), "f"(v.y), "f"(v.z), "f"(v.w) : "memory");
}

// ---------------- SGEMM: C[M,Nc] = A[M,128] @ B[128,Nc] ----------------
// 64x64 tile, BK=64 (2 k-tiles), 256 threads, 4x4 per thread.
__global__ __launch_bounds__(256) void sgemm_k128(
    const float* __restrict__ A, const float* __restrict__ B,
    float* __restrict__ C, int M, int Nc)
{
    __shared__ float As[64][68];   // [m][k], padded
    __shared__ float Bs[64][68];   // [k][n], padded
    const int tid = threadIdx.x;
    const int tx = tid & 15, ty = tid >> 4;
    const int row0 = blockIdx.y << 6;
    const int col0 = blockIdx.x << 6;
    float acc[4][4] = {};

    for (int kt = 0; kt < 128; kt += 64) {
        // A tile: 64 rows x 64 k, float4 coalesced
        #pragma unroll
        for (int i = tid; i < 64 * 16; i += 256) {
            int r = i >> 4, c4 = i & 15;
            int row = row0 + r;
            float4 v = make_float4(0.f, 0.f, 0.f, 0.f);
            if (row < M) v = *(const float4*)(A + row * 128 + kt + c4 * 4);
            *(float4*)&As[r][c4 * 4] = v;
        }
        // B tile: 64 k x 64 n, scalar guarded (handles Nc=47,188)
        #pragma unroll
        for (int i = tid; i < 64 * 64; i += 256) {
            int k = i >> 6, n = i & 63;
            int col = col0 + n;
            Bs[k][n] = (col < Nc) ? B[(kt + k) * Nc + col] : 0.f;
        }
        __syncthreads();
        #pragma unroll 16
        for (int k = 0; k < 64; ++k) {
            float a0 = As[ty * 4 + 0][k];
            float a1 = As[ty * 4 + 1][k];
            float a2 = As[ty * 4 + 2][k];
            float a3 = As[ty * 4 + 3][k];
            float4 b = *(const float4*)&Bs[k][tx * 4];
            acc[0][0] += a0 * b.x; acc[0][1] += a0 * b.y; acc[0][2] += a0 * b.z; acc[0][3] += a0 * b.w;
            acc[1][0] += a1 * b.x; acc[1][1] += a1 * b.y; acc[1][2] += a1 * b.z; acc[1][3] += a1 * b.w;
            acc[2][0] += a2 * b.x; acc[2][1] += a2 * b.y; acc[2][2] += a2 * b.z; acc[2][3] += a2 * b.w;
            acc[3][0] += a3 * b.x; acc[3][1] += a3 * b.y; acc[3][2] += a3 * b.z; acc[3][3] += a3 * b.w;
        }
        __syncthreads();
    }
    #pragma unroll
    for (int i = 0; i < 4; i++) {
        int row = row0 + ty * 4 + i;
        if (row >= M) continue;
        #pragma unroll
        for (int j = 0; j < 4; j++) {
            int col = col0 + tx * 4 + j;
            if (col < Nc) C[row * Nc + col] = acc[i][j];
        }
    }
}

// ---------------- per-node attention scores ----------------
__global__ void att_scores(const float* __restrict__ xh,
                           const float* __restrict__ ws,
                           const float* __restrict__ wd,
                           float* __restrict__ asrc, float* __restrict__ adst,
                           int C, int stride)
{
    int i = blockIdx.x * blockDim.x + threadIdx.x;
    if (i >= NN * 4) return;
    int node = i >> 2, h = i & 3;
    const float* row = xh + node * stride + h * C;
    const float* s_w = ws + h * C;
    const float* d_w = wd + h * C;
    float s1 = 0.f, s2 = 0.f;
    for (int c = 0; c < C; c++) {
        float v = row[c];
        s1 += v * s_w[c];
        s2 += v * d_w[c];
    }
    asrc[i] = s1;
    adst[i] = s2;
}

// ---------------- edge passes ----------------
__global__ void edge_max_k(const int* __restrict__ ei,
                           const float* __restrict__ asrc,
                           const float* __restrict__ adst,
                           unsigned* __restrict__ mbuf)
{
    int i = blockIdx.x * blockDim.x + threadIdx.x;
    if (i >= ETOT) return;
    int s, d;
    if (i < EE) { s = ei[i]; d = ei[EE + i]; } else { s = d = i - EE; }
    #pragma unroll
    for (int h = 0; h < 4; h++) {
        float e = lrelu(asrc[s * 4 + h] + adst[d * 4 + h]);
        atomicMax(&mbuf[d * 4 + h], fkey(e));
    }
}

__global__ void edge_sum_k(const int* __restrict__ ei,
                           const float* __restrict__ asrc,
                           const float* __restrict__ adst,
                           const unsigned* __restrict__ mbuf,
                           float* __restrict__ sbuf)
{
    int i = blockIdx.x * blockDim.x + threadIdx.x;
    if (i >= ETOT) return;
    int s, d;
    if (i < EE) { s = ei[i]; d = ei[EE + i]; } else { s = d = i - EE; }
    #pragma unroll
    for (int h = 0; h < 4; h++) {
        float e = lrelu(asrc[s * 4 + h] + adst[d * 4 + h]);
        atomicAdd(&sbuf[d * 4 + h], expf(e - funkey(mbuf[d * 4 + h])));
    }
}

// F = 128 (layers 0,1): one warp per edge, head = lane/8
__global__ void edge_scatter_128(const int* __restrict__ ei,
                                 const float* __restrict__ asrc,
                                 const float* __restrict__ adst,
                                 const unsigned* __restrict__ mbuf,
                                 const float* __restrict__ sbuf,
                                 const float* __restrict__ xh,
                                 float* __restrict__ outb)
{
    int gt = blockIdx.x * blockDim.x + threadIdx.x;
    int w = gt >> 5;
    if (w >= ETOT) return;
    int lane = gt & 31;
    int s, d;
    if (w < EE) { s = ei[w]; d = ei[EE + w]; } else { s = d = w - EE; }
    int h = lane >> 3;
    float e = lrelu(asrc[s * 4 + h] + adst[d * 4 + h]);
    float alpha = expf(e - funkey(mbuf[d * 4 + h])) / (sbuf[d * 4 + h] + 1e-16f);
    float4 v = *(const float4*)(xh + s * 128 + lane * 4);
    v.x *= alpha; v.y *= alpha; v.z *= alpha; v.w *= alpha;
    red4(outb + d * 128 + lane * 4, v);
}

// F = 188 (layer 2, C=47): one warp per edge, 47 float4 chunks
__global__ void edge_scatter_188(const int* __restrict__ ei,
                                 const float* __restrict__ asrc,
                                 const float* __restrict__ adst,
                                 const unsigned* __restrict__ mbuf,
                                 const float* __restrict__ sbuf,
                                 const float* __restrict__ xh,
                                 float* __restrict__ outb)
{
    int gt = blockIdx.x * blockDim.x + threadIdx.x;
    int w = gt >> 5;
    if (w >= ETOT) return;
    int lane = gt & 31;
    int s, d;
    if (w < EE) { s = ei[w]; d = ei[EE + w]; } else { s = d = w - EE; }
    float al[4];
    #pragma unroll
    for (int h = 0; h < 4; h++) {
        float e = lrelu(asrc[s * 4 + h] + adst[d * 4 + h]);
        al[h] = expf(e - funkey(mbuf[d * 4 + h])) / (sbuf[d * 4 + h] + 1e-16f);
    }
    const float* xr = xh + s * 188;
    float* orow = outb + d * 188;
    #pragma unroll
    for (int t = 0; t < 2; t++) {
        int idx = lane + t * 32;
        if (idx < 47) {
            int f0 = idx * 4;
            float4 v = *(const float4*)(xr + f0);
            v.x *= al[(f0 + 0) / 47];
            v.y *= al[(f0 + 1) / 47];
            v.z *= al[(f0 + 2) / 47];
            v.w *= al[(f0 + 3) / 47];
            red4(orow + f0, v);
        }
    }
}

// ---------------- finalize ----------------
__global__ void finalize_cat(const float* __restrict__ gat,
                             const float* __restrict__ skipv,
                             const float* __restrict__ bias,
                             const float* __restrict__ skip_b,
                             float* __restrict__ xout)
{
    int i = blockIdx.x * blockDim.x + threadIdx.x;
    if (i >= NN * 128) return;
    int f = i & 127;
    float v = gat[i] + skipv[i] + bias[f] + skip_b[f];
    xout[i] = v > 0.f ? v : expm1f(v);
}

__global__ void finalize_mean(const float* __restrict__ gat,   // [N,188]
                              const float* __restrict__ skipv, // [N,47]
                              const float* __restrict__ bias2,
                              const float* __restrict__ skip_b2,
                              float* __restrict__ out)          // [N,47]
{
    int i = blockIdx.x * blockDim.x + threadIdx.x;
    if (i >= NN * 47) return;
    int node = i / 47, o = i - node * 47;
    const float* g = gat + node * 188;
    float v = 0.25f * (g[o] + g[o + 47] + g[o + 94] + g[o + 141])
            + bias2[o] + skipv[i] + skip_b2[o];
    out[i] = v;
}

// ---------------- launch ----------------
extern "C" void kernel_launch(void* const* d_in, const int* in_sizes, int n_in,
                              void* d_out, int out_size)
{
    const float* x        = (const float*)d_in[0];
    const int*   ei       = (const int*)  d_in[1];
    const float* lin_w0   = (const float*)d_in[2];
    const float* att_src0 = (const float*)d_in[3];
    const float* att_dst0 = (const float*)d_in[4];
    const float* bias0    = (const float*)d_in[5];
    const float* skip_w0  = (const float*)d_in[6];
    const float* skip_b0  = (const float*)d_in[7];
    const float* lin_w1   = (const float*)d_in[8];
    const float* att_src1 = (const float*)d_in[9];
    const float* att_dst1 = (const float*)d_in[10];
    const float* bias1    = (const float*)d_in[11];
    const float* skip_w1  = (const float*)d_in[12];
    const float* skip_b1  = (const float*)d_in[13];
    const float* lin_w2   = (const float*)d_in[14];
    const float* att_src2 = (const float*)d_in[15];
    const float* att_dst2 = (const float*)d_in[16];
    const float* bias2    = (const float*)d_in[17];
    const float* skip_w2  = (const float*)d_in[18];
    const float* skip_b2  = (const float*)d_in[19];
    float* out = (float*)d_out;

    float *xh, *outb, *x1, *x2, *skipb, *asrc, *adst, *sbuf;
    unsigned* mbuf;
    cudaGetSymbolAddress((void**)&xh,    g_xh);
    cudaGetSymbolAddress((void**)&outb,  g_out);
    cudaGetSymbolAddress((void**)&x1,    g_x1);
    cudaGetSymbolAddress((void**)&x2,    g_x2);
    cudaGetSymbolAddress((void**)&skipb, g_skip);
    cudaGetSymbolAddress((void**)&asrc,  g_asrc);
    cudaGetSymbolAddress((void**)&adst,  g_adst);
    cudaGetSymbolAddress((void**)&mbuf,  g_m);
    cudaGetSymbolAddress((void**)&sbuf,  g_s);

    const int MB = (NN + 63) / 64;           // 782 row blocks
    const int EBLK = (ETOT + 255) / 256;
    const int WBLK = ((long long)ETOT * 32 + 255) / 256;

    // ---------- layer 0 ----------
    sgemm_k128<<<dim3(2, MB), 256>>>(x, lin_w0, xh, NN, 128);
    sgemm_k128<<<dim3(2, MB), 256>>>(x, skip_w0, skipb, NN, 128);
    att_scores<<<(NN * 4 + 255) / 256, 256>>>(xh, att_src0, att_dst0, asrc, adst, 32, 128);
    cudaMemsetAsync(mbuf, 0, NN * 4 * sizeof(unsigned));
    cudaMemsetAsync(sbuf, 0, NN * 4 * sizeof(float));
    cudaMemsetAsync(outb, 0, NN * 128 * sizeof(float));
    edge_max_k<<<EBLK, 256>>>(ei, asrc, adst, mbuf);
    edge_sum_k<<<EBLK, 256>>>(ei, asrc, adst, mbuf, sbuf);
    edge_scatter_128<<<WBLK, 256>>>(ei, asrc, adst, mbuf, sbuf, xh, outb);
    finalize_cat<<<(NN * 128 + 255) / 256, 256>>>(outb, skipb, bias0, skip_b0, x1);

    // ---------- layer 1 ----------
    sgemm_k128<<<dim3(2, MB), 256>>>(x1, lin_w1, xh, NN, 128);
    sgemm_k128<<<dim3(2, MB), 256>>>(x1, skip_w1, skipb, NN, 128);
    att_scores<<<(NN * 4 + 255) / 256, 256>>>(xh, att_src1, att_dst1, asrc, adst, 32, 128);
    cudaMemsetAsync(mbuf, 0, NN * 4 * sizeof(unsigned));
    cudaMemsetAsync(sbuf, 0, NN * 4 * sizeof(float));
    cudaMemsetAsync(outb, 0, NN * 128 * sizeof(float));
    edge_max_k<<<EBLK, 256>>>(ei, asrc, adst, mbuf);
    edge_sum_k<<<EBLK, 256>>>(ei, asrc, adst, mbuf, sbuf);
    edge_scatter_128<<<WBLK, 256>>>(ei, asrc, adst, mbuf, sbuf, xh, outb);
    finalize_cat<<<(NN * 128 + 255) / 256, 256>>>(outb, skipb, bias1, skip_b1, x2);

    // ---------- layer 2 ----------
    sgemm_k128<<<dim3(3, MB), 256>>>(x2, lin_w2, xh, NN, 188);
    sgemm_k128<<<dim3(1, MB), 256>>>(x2, skip_w2, skipb, NN, 47);
    att_scores<<<(NN * 4 + 255) / 256, 256>>>(xh, att_src2, att_dst2, asrc, adst, 47, 188);
    cudaMemsetAsync(mbuf, 0, NN * 4 * sizeof(unsigned));
    cudaMemsetAsync(sbuf, 0, NN * 4 * sizeof(float));
    cudaMemsetAsync(outb, 0, NN * 188 * sizeof(float));
    edge_max_k<<<EBLK, 256>>>(ei, asrc, adst, mbuf);
    edge_sum_k<<<EBLK, 256>>>(ei, asrc, adst, mbuf, sbuf);
    edge_scatter_188<<<WBLK, 256>>>(ei, asrc, adst, mbuf, sbuf, xh, outb);
    finalize_mean<<<(NN * 47 + 255) / 256, 256>>>(outb, skipb, bias2, skip_b2, out);
}

// round 6
// speedup vs baseline: 1.4676x; 1.4676x over previous
#include <cuda_runtime.h>
#include <cuda_bf16.h>
#include <math.h>

#define NN 50000
#define EE 800000
#define ETOT (EE + NN)
#define NB_SCAN 196   // ceil(50000/256)

// ---------------- scratch (no allocations allowed) ----------------
__device__ float    g_xh  [NN * 188];   // lin output (max width 188)
__device__ float    g_x1  [NN * 128];   // layer0 output
__device__ float    g_x2  [NN * 128];   // layer1 output
__device__ float    g_skip[NN * 128];   // skip GEMM output (max width 128)
__device__ float    g_asrc[NN * 4];
__device__ float    g_adst[NN * 4];
// CSR scratch
__device__ int      g_deg   [NN];
__device__ int      g_ex    [NN];
__device__ int      g_bsum  [256];
__device__ int      g_bpre  [256];
__device__ int      g_rowptr[NN + 1];
__device__ int      g_cursor[NN];
__device__ int      g_csr   [ETOT];

// ---------------- helpers ----------------
__device__ __forceinline__ float lrelu(float e) { return fmaxf(e, 0.2f * e); }

__device__ __forceinline__ unsigned long long pack2(float x, float y) {
    unsigned long long r;
    asm("mov.b64 %0, {%1, %2};" : "=l"(r) : "f"(x), "f"(y));
    return r;
}
__device__ __forceinline__ float2 unpack2(unsigned long long v) {
    float2 r;
    asm("mov.b64 {%0, %1}, %2;" : "=f"(r.x), "=f"(r.y) : "l"(v));
    return r;
}
__device__ __forceinline__ void ffma2(unsigned long long& acc,
                                      unsigned long long a, unsigned long long b) {
    asm("fma.rn.f32x2 %0, %1, %2, %0;" : "+l"(acc) : "l"(a), "l"(b));
}

// ================= CSR build =================
__global__ void k_count(const int* __restrict__ ei, int* __restrict__ deg) {
    int i = blockIdx.x * blockDim.x + threadIdx.x;
    if (i >= ETOT) return;
    int d = (i < EE) ? ei[EE + i] : i - EE;
    atomicAdd(&deg[d], 1);
}

__global__ void k_scan1(const int* __restrict__ deg, int* __restrict__ ex,
                        int* __restrict__ bsum) {
    __shared__ int sh[256];
    int t = threadIdx.x;
    int i = blockIdx.x * 256 + t;
    int v = (i < NN) ? deg[i] : 0;
    sh[t] = v;
    __syncthreads();
    for (int off = 1; off < 256; off <<= 1) {
        int a = (t >= off) ? sh[t - off] : 0;
        __syncthreads();
        sh[t] += a;
        __syncthreads();
    }
    if (i < NN) ex[i] = sh[t] - v;
    if (t == 255) bsum[blockIdx.x] = sh[255];
}

__global__ void k_scan2(const int* __restrict__ bsum, int* __restrict__ bpre) {
    __shared__ int sh[256];
    int t = threadIdx.x;
    int v = (t < NB_SCAN) ? bsum[t] : 0;
    sh[t] = v;
    __syncthreads();
    for (int off = 1; off < 256; off <<= 1) {
        int a = (t >= off) ? sh[t - off] : 0;
        __syncthreads();
        sh[t] += a;
        __syncthreads();
    }
    bpre[t] = sh[t] - v;
}

__global__ void k_scan3(const int* __restrict__ ex, const int* __restrict__ bpre,
                        int* __restrict__ rowptr, int* __restrict__ cursor) {
    int i = blockIdx.x * blockDim.x + threadIdx.x;
    if (i < NN) {
        int r = ex[i] + bpre[i >> 8];
        rowptr[i] = r;
        cursor[i] = r;
    }
    if (i == 0) rowptr[NN] = ETOT;
}

__global__ void k_fill(const int* __restrict__ ei, int* __restrict__ cursor,
                       int* __restrict__ csr) {
    int i = blockIdx.x * blockDim.x + threadIdx.x;
    if (i >= ETOT) return;
    int s, d;
    if (i < EE) { s = ei[i]; d = ei[EE + i]; } else { s = d = i - EE; }
    int pos = atomicAdd(&cursor[d], 1);
    csr[pos] = s;
}

// ================= SGEMM v2: C[M,Nc] = A[M,128] @ B[128,Nc] =================
// 128x64 tile, BK=32, 256 threads, 8x4 per thread via fma.rn.f32x2.
__global__ __launch_bounds__(256) void sgemm_k128(
    const float* __restrict__ A, const float* __restrict__ B,
    float* __restrict__ C, int M, int Nc)
{
    __shared__ float At[32][132];  // [k][m], stride 132 (8B-aligned pairs)
    __shared__ float Bs[32][68];   // [k][n]
    const int tid = threadIdx.x;
    const int tx = tid & 15, ty = tid >> 4;
    const int row0 = blockIdx.y << 7;
    const int col0 = blockIdx.x << 6;

    unsigned long long acc[4][4];  // [row-pair][col] : (row 2i, row 2i+1)
    #pragma unroll
    for (int i = 0; i < 4; i++)
        #pragma unroll
        for (int j = 0; j < 4; j++) acc[i][j] = 0ull;

    #pragma unroll 1
    for (int kt = 0; kt < 128; kt += 32) {
        // A tile: 128 rows x 32 k, float4 global loads, transposed store
        #pragma unroll
        for (int jj = 0; jj < 4; jj++) {
            int i = tid + 256 * jj;           // 0..1023
            int r = i >> 3, kq = i & 7;
            int row = row0 + r;
            float4 v = make_float4(0.f, 0.f, 0.f, 0.f);
            if (row < M) v = *(const float4*)(A + row * 128 + kt + kq * 4);
            At[kq * 4 + 0][r] = v.x;
            At[kq * 4 + 1][r] = v.y;
            At[kq * 4 + 2][r] = v.z;
            At[kq * 4 + 3][r] = v.w;
        }
        // B tile: 32 k x 64 n, scalar guarded
        #pragma unroll
        for (int jj = 0; jj < 8; jj++) {
            int i = tid + 256 * jj;           // 0..2047
            int k = i >> 6, n = i & 63;
            int col = col0 + n;
            Bs[k][n] = (col < Nc) ? B[(kt + k) * Nc + col] : 0.f;
        }
        __syncthreads();
        #pragma unroll
        for (int k = 0; k < 32; ++k) {
            const float2* ap = (const float2*)&At[k][ty * 8];
            unsigned long long a0 = pack2(ap[0].x, ap[0].y);
            unsigned long long a1 = pack2(ap[1].x, ap[1].y);
            unsigned long long a2 = pack2(ap[2].x, ap[2].y);
            unsigned long long a3 = pack2(ap[3].x, ap[3].y);
            float4 b = *(const float4*)&Bs[k][tx * 4];
            unsigned long long b0 = pack2(b.x, b.x);
            unsigned long long b1 = pack2(b.y, b.y);
            unsigned long long b2 = pack2(b.z, b.z);
            unsigned long long b3 = pack2(b.w, b.w);
            ffma2(acc[0][0], a0, b0); ffma2(acc[0][1], a0, b1);
            ffma2(acc[0][2], a0, b2); ffma2(acc[0][3], a0, b3);
            ffma2(acc[1][0], a1, b0); ffma2(acc[1][1], a1, b1);
            ffma2(acc[1][2], a1, b2); ffma2(acc[1][3], a1, b3);
            ffma2(acc[2][0], a2, b0); ffma2(acc[2][1], a2, b1);
            ffma2(acc[2][2], a2, b2); ffma2(acc[2][3], a2, b3);
            ffma2(acc[3][0], a3, b0); ffma2(acc[3][1], a3, b1);
            ffma2(acc[3][2], a3, b2); ffma2(acc[3][3], a3, b3);
        }
        __syncthreads();
    }
    #pragma unroll
    for (int i = 0; i < 4; i++) {
        int r0 = row0 + ty * 8 + 2 * i;
        #pragma unroll
        for (int j = 0; j < 4; j++) {
            int col = col0 + tx * 4 + j;
            if (col >= Nc) continue;
            float2 v = unpack2(acc[i][j]);
            if (r0 < M)     C[r0 * Nc + col]       = v.x;
            if (r0 + 1 < M) C[(r0 + 1) * Nc + col] = v.y;
        }
    }
}

// ---------------- per-node attention scores ----------------
__global__ void att_scores(const float* __restrict__ xh,
                           const float* __restrict__ ws,
                           const float* __restrict__ wd,
                           float* __restrict__ asrc, float* __restrict__ adst,
                           int C, int stride)
{
    int i = blockIdx.x * blockDim.x + threadIdx.x;
    if (i >= NN * 4) return;
    int node = i >> 2, h = i & 3;
    const float* row = xh + node * stride + h * C;
    const float* s_w = ws + h * C;
    const float* d_w = wd + h * C;
    float s1 = 0.f, s2 = 0.f;
    for (int c = 0; c < C; c++) {
        float v = row[c];
        s1 += v * s_w[c];
        s2 += v * d_w[c];
    }
    asrc[i] = s1;
    adst[i] = s2;
}

// ================= fused GAT aggregation (F=128) =================
// warp per dst node; pass1 max, pass2 sum-exp + weighted gather; fused
// skip + bias + ELU epilogue. No atomics, no scratch output buffer.
__global__ __launch_bounds__(256) void gat_agg_128(
    const int* __restrict__ rowptr, const int* __restrict__ csr,
    const float* __restrict__ asrc, const float* __restrict__ adst,
    const float* __restrict__ xh, const float* __restrict__ skipb,
    const float* __restrict__ bias, const float* __restrict__ skip_b,
    float* __restrict__ xout)
{
    int w = (blockIdx.x * blockDim.x + threadIdx.x) >> 5;
    if (w >= NN) return;
    int lane = threadIdx.x & 31;
    int beg = rowptr[w], end = rowptr[w + 1];
    float4 ad = *(const float4*)(adst + 4 * w);

    float4 m = make_float4(-1e30f, -1e30f, -1e30f, -1e30f);
    for (int e = beg; e < end; e++) {
        int s = csr[e];
        float4 a = *(const float4*)(asrc + 4 * s);
        m.x = fmaxf(m.x, lrelu(a.x + ad.x));
        m.y = fmaxf(m.y, lrelu(a.y + ad.y));
        m.z = fmaxf(m.z, lrelu(a.z + ad.z));
        m.w = fmaxf(m.w, lrelu(a.w + ad.w));
    }

    int h = lane >> 3;
    float4 ws = make_float4(0.f, 0.f, 0.f, 0.f);
    float4 acc = make_float4(0.f, 0.f, 0.f, 0.f);
    for (int e = beg; e < end; e++) {
        int s = csr[e];
        float4 a = *(const float4*)(asrc + 4 * s);
        float wx = __expf(lrelu(a.x + ad.x) - m.x);
        float wy = __expf(lrelu(a.y + ad.y) - m.y);
        float wz = __expf(lrelu(a.z + ad.z) - m.z);
        float ww = __expf(lrelu(a.w + ad.w) - m.w);
        ws.x += wx; ws.y += wy; ws.z += wz; ws.w += ww;
        float wl = (h == 0) ? wx : (h == 1) ? wy : (h == 2) ? wz : ww;
        float4 v = *(const float4*)(xh + (long long)s * 128 + lane * 4);
        acc.x += wl * v.x; acc.y += wl * v.y; acc.z += wl * v.z; acc.w += wl * v.w;
    }
    float wsh = (h == 0) ? ws.x : (h == 1) ? ws.y : (h == 2) ? ws.z : ws.w;
    float inv = 1.f / (wsh + 1e-16f);

    int base = w * 128 + lane * 4;
    float4 sk = *(const float4*)(skipb + base);
    float4 bi = *(const float4*)(bias + lane * 4);
    float4 sb = *(const float4*)(skip_b + lane * 4);
    float4 o;
    o.x = acc.x * inv + sk.x + bi.x + sb.x;
    o.y = acc.y * inv + sk.y + bi.y + sb.y;
    o.z = acc.z * inv + sk.z + bi.z + sb.z;
    o.w = acc.w * inv + sk.w + bi.w + sb.w;
    o.x = o.x > 0.f ? o.x : expm1f(o.x);
    o.y = o.y > 0.f ? o.y : expm1f(o.y);
    o.z = o.z > 0.f ? o.z : expm1f(o.z);
    o.w = o.w > 0.f ? o.w : expm1f(o.w);
    *(float4*)(xout + base) = o;
}

// ================= fused GAT aggregation (layer 2, F=188, head-mean) ======
// warp per dst node; lane owns output cols {lane, lane+32} (<47).
__global__ __launch_bounds__(256) void gat_agg_188(
    const int* __restrict__ rowptr, const int* __restrict__ csr,
    const float* __restrict__ asrc, const float* __restrict__ adst,
    const float* __restrict__ xh, const float* __restrict__ skipb,
    const float* __restrict__ bias2, const float* __restrict__ skip_b2,
    float* __restrict__ out)
{
    int w = (blockIdx.x * blockDim.x + threadIdx.x) >> 5;
    if (w >= NN) return;
    int lane = threadIdx.x & 31;
    int beg = rowptr[w], end = rowptr[w + 1];
    float4 ad = *(const float4*)(adst + 4 * w);

    float4 m = make_float4(-1e30f, -1e30f, -1e30f, -1e30f);
    for (int e = beg; e < end; e++) {
        int s = csr[e];
        float4 a = *(const float4*)(asrc + 4 * s);
        m.x = fmaxf(m.x, lrelu(a.x + ad.x));
        m.y = fmaxf(m.y, lrelu(a.y + ad.y));
        m.z = fmaxf(m.z, lrelu(a.z + ad.z));
        m.w = fmaxf(m.w, lrelu(a.w + ad.w));
    }

    float4 ws = make_float4(0.f, 0.f, 0.f, 0.f);
    float a00 = 0.f, a01 = 0.f, a02 = 0.f, a03 = 0.f;  // chunk 0, heads 0..3
    float a10 = 0.f, a11 = 0.f, a12 = 0.f, a13 = 0.f;  // chunk 1
    int o1 = lane + 32;
    for (int e = beg; e < end; e++) {
        int s = csr[e];
        float4 a = *(const float4*)(asrc + 4 * s);
        float wx = __expf(lrelu(a.x + ad.x) - m.x);
        float wy = __expf(lrelu(a.y + ad.y) - m.y);
        float wz = __expf(lrelu(a.z + ad.z) - m.z);
        float ww = __expf(lrelu(a.w + ad.w) - m.w);
        ws.x += wx; ws.y += wy; ws.z += wz; ws.w += ww;
        const float* row = xh + (long long)s * 188;
        a00 += wx * row[lane];
        a01 += wy * row[47 + lane];
        a02 += wz * row[94 + lane];
        a03 += ww * row[141 + lane];
        if (o1 < 47) {
            a10 += wx * row[o1];
            a11 += wy * row[47 + o1];
            a12 += wz * row[94 + o1];
            a13 += ww * row[141 + o1];
        }
    }
    float ix = 1.f / (ws.x + 1e-16f);
    float iy = 1.f / (ws.y + 1e-16f);
    float iz = 1.f / (ws.z + 1e-16f);
    float iw = 1.f / (ws.w + 1e-16f);

    {
        int o = lane;
        float v = 0.25f * (a00 * ix + a01 * iy + a02 * iz + a03 * iw);
        out[w * 47 + o] = v + bias2[o] + skipb[w * 47 + o] + skip_b2[o];
    }
    if (o1 < 47) {
        float v = 0.25f * (a10 * ix + a11 * iy + a12 * iz + a13 * iw);
        out[w * 47 + o1] = v + bias2[o1] + skipb[w * 47 + o1] + skip_b2[o1];
    }
}

// ---------------- launch ----------------
extern "C" void kernel_launch(void* const* d_in, const int* in_sizes, int n_in,
                              void* d_out, int out_size)
{
    const float* x        = (const float*)d_in[0];
    const int*   ei       = (const int*)  d_in[1];
    const float* lin_w0   = (const float*)d_in[2];
    const float* att_src0 = (const float*)d_in[3];
    const float* att_dst0 = (const float*)d_in[4];
    const float* bias0    = (const float*)d_in[5];
    const float* skip_w0  = (const float*)d_in[6];
    const float* skip_b0  = (const float*)d_in[7];
    const float* lin_w1   = (const float*)d_in[8];
    const float* att_src1 = (const float*)d_in[9];
    const float* att_dst1 = (const float*)d_in[10];
    const float* bias1    = (const float*)d_in[11];
    const float* skip_w1  = (const float*)d_in[12];
    const float* skip_b1  = (const float*)d_in[13];
    const float* lin_w2   = (const float*)d_in[14];
    const float* att_src2 = (const float*)d_in[15];
    const float* att_dst2 = (const float*)d_in[16];
    const float* bias2    = (const float*)d_in[17];
    const float* skip_w2  = (const float*)d_in[18];
    const float* skip_b2  = (const float*)d_in[19];
    float* out = (float*)d_out;

    float *xh, *x1, *x2, *skipb, *asrc, *adst;
    int *deg, *ex, *bsum, *bpre, *rowptr, *cursor, *csr;
    cudaGetSymbolAddress((void**)&xh,     g_xh);
    cudaGetSymbolAddress((void**)&x1,     g_x1);
    cudaGetSymbolAddress((void**)&x2,     g_x2);
    cudaGetSymbolAddress((void**)&skipb,  g_skip);
    cudaGetSymbolAddress((void**)&asrc,   g_asrc);
    cudaGetSymbolAddress((void**)&adst,   g_adst);
    cudaGetSymbolAddress((void**)&deg,    g_deg);
    cudaGetSymbolAddress((void**)&ex,     g_ex);
    cudaGetSymbolAddress((void**)&bsum,   g_bsum);
    cudaGetSymbolAddress((void**)&bpre,   g_bpre);
    cudaGetSymbolAddress((void**)&rowptr, g_rowptr);
    cudaGetSymbolAddress((void**)&cursor, g_cursor);
    cudaGetSymbolAddress((void**)&csr,    g_csr);

    const int MB   = (NN + 127) / 128;               // 391 row blocks
    const int EBLK = (ETOT + 255) / 256;             // 3321
    const int WGRD = (NN * 32 + 255) / 256;          // 6250 (warp per node)

    // ---------- CSR build (once, shared by all 3 layers) ----------
    cudaMemsetAsync(deg, 0, NN * sizeof(int));
    k_count<<<EBLK, 256>>>(ei, deg);
    k_scan1<<<NB_SCAN, 256>>>(deg, ex, bsum);
    k_scan2<<<1, 256>>>(bsum, bpre);
    k_scan3<<<(NN + 255) / 256, 256>>>(ex, bpre, rowptr, cursor);
    k_fill<<<EBLK, 256>>>(ei, cursor, csr);

    // ---------- layer 0 ----------
    sgemm_k128<<<dim3(2, MB), 256>>>(x, lin_w0, xh, NN, 128);
    sgemm_k128<<<dim3(2, MB), 256>>>(x, skip_w0, skipb, NN, 128);
    att_scores<<<(NN * 4 + 255) / 256, 256>>>(xh, att_src0, att_dst0, asrc, adst, 32, 128);
    gat_agg_128<<<WGRD, 256>>>(rowptr, csr, asrc, adst, xh, skipb, bias0, skip_b0, x1);

    // ---------- layer 1 ----------
    sgemm_k128<<<dim3(2, MB), 256>>>(x1, lin_w1, xh, NN, 128);
    sgemm_k128<<<dim3(2, MB), 256>>>(x1, skip_w1, skipb, NN, 128);
    att_scores<<<(NN * 4 + 255) / 256, 256>>>(xh, att_src1, att_dst1, asrc, adst, 32, 128);
    gat_agg_128<<<WGRD, 256>>>(rowptr, csr, asrc, adst, xh, skipb, bias1, skip_b1, x2);

    // ---------- layer 2 ----------
    sgemm_k128<<<dim3(3, MB), 256>>>(x2, lin_w2, xh, NN, 188);
    sgemm_k128<<<dim3(1, MB), 256>>>(x2, skip_w2, skipb, NN, 47);
    att_scores<<<(NN * 4 + 255) / 256, 256>>>(xh, att_src2, att_dst2, asrc, adst, 47, 188);
    gat_agg_188<<<WGRD, 256>>>(rowptr, csr, asrc, adst, xh, skipb, bias2, skip_b2, out);
}

// round 9
// speedup vs baseline: 1.7724x; 1.2077x over previous
#include <cuda_runtime.h>
#include <cuda_bf16.h>
#include <math.h>
#include <stdint.h>

#define NN 50000
#define EE 800000
#define ETOT (EE + NN)
#define NB_SCAN 196   // ceil(50000/256)

// ---------------- scratch (no allocations allowed) ----------------
__device__ float    g_xh  [NN * 188];   // lin output (max width 188)
__device__ float    g_x1  [NN * 128];   // layer0 output
__device__ float    g_x2  [NN * 128];   // layer1 output
__device__ float    g_skip[NN * 128];   // skip GEMM output (max width 128)
__device__ float    g_asrc[NN * 4];
__device__ float    g_adst[NN * 4];
// CSR scratch
__device__ int      g_deg   [NN];
__device__ int      g_ex    [NN];
__device__ int      g_bsum  [256];
__device__ int      g_bpre  [256];
__device__ int      g_rowptr[NN + 1];
__device__ int      g_cursor[NN];
__device__ int      g_csr   [ETOT];

// ---------------- helpers ----------------
__device__ __forceinline__ float lrelu(float e) { return fmaxf(e, 0.2f * e); }

__device__ __forceinline__ uint32_t smem_u32(const void* p) {
    uint32_t a;
    asm("{ .reg .u64 t; cvta.to.shared.u64 t, %1; cvt.u32.u64 %0, t; }"
        : "=r"(a) : "l"(p));
    return a;
}

__device__ __forceinline__ void split_bf16(float v, __nv_bfloat16& h, __nv_bfloat16& l) {
    h = __float2bfloat16_rn(v);
    l = __float2bfloat16_rn(v - __bfloat162float(h));
}

__device__ __forceinline__ uint32_t pack_bf16(__nv_bfloat16 a, __nv_bfloat16 b) {
    return (uint32_t)__bfloat16_as_ushort(a) |
           ((uint32_t)__bfloat16_as_ushort(b) << 16);
}

__device__ __forceinline__ void ldsm_x4(uint32_t& r0, uint32_t& r1,
                                        uint32_t& r2, uint32_t& r3, uint32_t addr) {
    asm volatile("ldmatrix.sync.aligned.m8n8.x4.shared.b16 {%0,%1,%2,%3}, [%4];"
                 : "=r"(r0), "=r"(r1), "=r"(r2), "=r"(r3) : "r"(addr));
}

__device__ __forceinline__ void mma_bf16(float* c, const uint32_t* a, const uint32_t* b) {
    asm volatile(
        "mma.sync.aligned.m16n8k16.row.col.f32.bf16.bf16.f32 "
        "{%0,%1,%2,%3}, {%4,%5,%6,%7}, {%8,%9}, {%0,%1,%2,%3};"
        : "+f"(c[0]), "+f"(c[1]), "+f"(c[2]), "+f"(c[3])
        : "r"(a[0]), "r"(a[1]), "r"(a[2]), "r"(a[3]), "r"(b[0]), "r"(b[1]));
}

// SMEM layout (bytes), stride 136 bf16 = 272B per row
#define AST       136
#define BST       136
#define SM_AHI    0
#define SM_ALO    (128 * AST * 2)                 // 34816
#define SM_BHI    (SM_ALO + 128 * AST * 2)        // 69632
#define SM_BLO    (SM_BHI + 256 * BST * 2)        // 139264
#define SM_TOTAL  (SM_BLO + 256 * BST * 2)        // 208896

// ================= CSR build =================
__global__ void k_count(const int* __restrict__ ei, int* __restrict__ deg) {
    int i = blockIdx.x * blockDim.x + threadIdx.x;
    if (i >= ETOT) return;
    int d = (i < EE) ? ei[EE + i] : i - EE;
    atomicAdd(&deg[d], 1);
}
__global__ void k_scan1(const int* __restrict__ deg, int* __restrict__ ex,
                        int* __restrict__ bsum) {
    __shared__ int sh[256];
    int t = threadIdx.x;
    int i = blockIdx.x * 256 + t;
    int v = (i < NN) ? deg[i] : 0;
    sh[t] = v;
    __syncthreads();
    for (int off = 1; off < 256; off <<= 1) {
        int a = (t >= off) ? sh[t - off] : 0;
        __syncthreads();
        sh[t] += a;
        __syncthreads();
    }
    if (i < NN) ex[i] = sh[t] - v;
    if (t == 255) bsum[blockIdx.x] = sh[255];
}
__global__ void k_scan2(const int* __restrict__ bsum, int* __restrict__ bpre) {
    __shared__ int sh[256];
    int t = threadIdx.x;
    int v = (t < NB_SCAN) ? bsum[t] : 0;
    sh[t] = v;
    __syncthreads();
    for (int off = 1; off < 256; off <<= 1) {
        int a = (t >= off) ? sh[t - off] : 0;
        __syncthreads();
        sh[t] += a;
        __syncthreads();
    }
    bpre[t] = sh[t] - v;
}
__global__ void k_scan3(const int* __restrict__ ex, const int* __restrict__ bpre,
                        int* __restrict__ rowptr, int* __restrict__ cursor) {
    int i = blockIdx.x * blockDim.x + threadIdx.x;
    if (i < NN) {
        int r = ex[i] + bpre[i >> 8];
        rowptr[i] = r;
        cursor[i] = r;
    }
    if (i == 0) rowptr[NN] = ETOT;
}
__global__ void k_fill(const int* __restrict__ ei, int* __restrict__ cursor,
                       int* __restrict__ csr) {
    int i = blockIdx.x * blockDim.x + threadIdx.x;
    if (i >= ETOT) return;
    int s, d;
    if (i < EE) { s = ei[i]; d = ei[EE + i]; } else { s = d = i - EE; }
    int pos = atomicAdd(&cursor[d], 1);
    csr[pos] = s;
}

// ============ shared staging + mainloop for the mma.sync GEMMs ============
// A[128,128] f32 -> Ahi/Alo bf16 smem; B (transposed, n-major) 256 rows.
__device__ __forceinline__ void stage_A(char* sm, const float* __restrict__ A,
                                        int row0, int tid) {
    #pragma unroll
    for (int jj = 0; jj < 8; jj++) {
        int idx = tid + jj * 512;            // 0..4095
        int r = idx >> 5, q = idx & 31;      // row, float4 index
        int row = row0 + r;
        float4 v = make_float4(0.f, 0.f, 0.f, 0.f);
        if (row < NN) v = *(const float4*)(A + (long long)row * 128 + q * 4);
        __nv_bfloat16 h0, l0, h1, l1, h2, l2, h3, l3;
        split_bf16(v.x, h0, l0); split_bf16(v.y, h1, l1);
        split_bf16(v.z, h2, l2); split_bf16(v.w, h3, l3);
        uint2 hi, lo;
        hi.x = pack_bf16(h0, h1);
        hi.y = pack_bf16(h2, h3);
        lo.x = pack_bf16(l0, l1);
        lo.y = pack_bf16(l2, l3);
        *(uint2*)(sm + SM_AHI + r * (AST * 2) + q * 8) = hi;
        *(uint2*)(sm + SM_ALO + r * (AST * 2) + q * 8) = lo;
    }
}

// mainloop: 8 k-steps, 3 passes; warp tile 32x64 (2 m-tiles x 8 n-tiles)
__device__ __forceinline__ void mma_mainloop(char* sm, float acc[2][8][4],
                                             int wid, int lane) {
    const uint32_t sb = smem_u32(sm);
    const int wm = wid >> 2, wn = wid & 3;
    const int m0r = wm * 32, n0 = wn * 64;
    // lane patterns
    const int ar = (lane & 15), ak = (lane >> 4) * 8;          // A ldmatrix
    const int bn = ((lane >> 4) * 8) + (lane & 7);             // B ldmatrix n-offset
    const int bk = ((lane >> 3) & 1) * 8;                      // B ldmatrix k-offset

    #pragma unroll
    for (int ks = 0; ks < 8; ks++) {
        int k0 = ks * 16;
        uint32_t ahi[2][4], alo[2][4], bhi[8][2], blo[8][2];
        #pragma unroll
        for (int mt = 0; mt < 2; mt++) {
            uint32_t addr = sb + SM_AHI + (m0r + mt * 16 + ar) * (AST * 2) + (k0 + ak) * 2;
            ldsm_x4(ahi[mt][0], ahi[mt][1], ahi[mt][2], ahi[mt][3], addr);
        }
        #pragma unroll
        for (int p = 0; p < 4; p++) {
            uint32_t addr = sb + SM_BHI + (n0 + p * 16 + bn) * (BST * 2) + (k0 + bk) * 2;
            ldsm_x4(bhi[2 * p][0], bhi[2 * p][1], bhi[2 * p + 1][0], bhi[2 * p + 1][1], addr);
        }
        #pragma unroll
        for (int mt = 0; mt < 2; mt++)
            #pragma unroll
            for (int nt = 0; nt < 8; nt++)
                mma_bf16(acc[mt][nt], ahi[mt], bhi[nt]);
        #pragma unroll
        for (int p = 0; p < 4; p++) {
            uint32_t addr = sb + SM_BLO + (n0 + p * 16 + bn) * (BST * 2) + (k0 + bk) * 2;
            ldsm_x4(blo[2 * p][0], blo[2 * p][1], blo[2 * p + 1][0], blo[2 * p + 1][1], addr);
        }
        #pragma unroll
        for (int mt = 0; mt < 2; mt++)
            #pragma unroll
            for (int nt = 0; nt < 8; nt++)
                mma_bf16(acc[mt][nt], ahi[mt], blo[nt]);
        #pragma unroll
        for (int mt = 0; mt < 2; mt++) {
            uint32_t addr = sb + SM_ALO + (m0r + mt * 16 + ar) * (AST * 2) + (k0 + ak) * 2;
            ldsm_x4(alo[mt][0], alo[mt][1], alo[mt][2], alo[mt][3], addr);
        }
        #pragma unroll
        for (int mt = 0; mt < 2; mt++)
            #pragma unroll
            for (int nt = 0; nt < 8; nt++)
                mma_bf16(acc[mt][nt], alo[mt], bhi[nt]);
    }
}

// ================= dual GEMM, layers 0/1 (mma.sync bf16 split-3) ==========
// C[128,256] = A[128,128] @ [Wlin | Wskip]
__global__ __launch_bounds__(512, 1) void gemm_dual_128(
    const float* __restrict__ A, const float* __restrict__ Wlin,
    const float* __restrict__ Wskip, float* __restrict__ Olin,
    float* __restrict__ Oskip)
{
    extern __shared__ char sm[];
    const int tid = threadIdx.x;
    const int wid = tid >> 5, lane = tid & 31;
    const int row0 = blockIdx.x << 7;

    stage_A(sm, A, row0, tid);
    // B: 256 n-rows x 128 k, transposed, k-pairs per thread
    #pragma unroll
    for (int jj = 0; jj < 32; jj++) {
        int idx = tid + jj * 512;            // 0..16383
        int kp = idx >> 8, n = idx & 255;
        int k = kp * 2;
        float v0, v1;
        if (n < 128) { v0 = Wlin[k * 128 + n];  v1 = Wlin[(k + 1) * 128 + n]; }
        else { int j = n - 128; v0 = Wskip[k * 128 + j]; v1 = Wskip[(k + 1) * 128 + j]; }
        __nv_bfloat16 h0, l0, h1, l1;
        split_bf16(v0, h0, l0); split_bf16(v1, h1, l1);
        *(uint32_t*)(sm + SM_BHI + n * (BST * 2) + kp * 4) = pack_bf16(h0, h1);
        *(uint32_t*)(sm + SM_BLO + n * (BST * 2) + kp * 4) = pack_bf16(l0, l1);
    }
    __syncthreads();

    float acc[2][8][4];
    #pragma unroll
    for (int i = 0; i < 2; i++)
        #pragma unroll
        for (int j = 0; j < 8; j++)
            #pragma unroll
            for (int q = 0; q < 4; q++) acc[i][j][q] = 0.f;

    mma_mainloop(sm, acc, wid, lane);

    // epilogue
    const int wm = wid >> 2, wn = wid & 3;
    const int g = lane >> 2, t = lane & 3;
    #pragma unroll
    for (int mt = 0; mt < 2; mt++) {
        #pragma unroll
        for (int half = 0; half < 2; half++) {
            int row = row0 + wm * 32 + mt * 16 + g + half * 8;
            if (row >= NN) continue;
            #pragma unroll
            for (int nt = 0; nt < 8; nt++) {
                int c = wn * 64 + nt * 8 + t * 2;
                float2 v;
                v.x = acc[mt][nt][half * 2 + 0];
                v.y = acc[mt][nt][half * 2 + 1];
                if (c < 128) *(float2*)(Olin + (long long)row * 128 + c) = v;
                else         *(float2*)(Oskip + (long long)row * 128 + (c - 128)) = v;
            }
        }
    }
}

// ================= layer-2 GEMM (N: 188 lin @0, 47 skip @192) =============
__global__ __launch_bounds__(512, 1) void gemm_l2(
    const float* __restrict__ A, const float* __restrict__ Wlin,
    const float* __restrict__ Wskip, float* __restrict__ Olin,
    float* __restrict__ Oskip)
{
    extern __shared__ char sm[];
    const int tid = threadIdx.x;
    const int wid = tid >> 5, lane = tid & 31;
    const int row0 = blockIdx.x << 7;

    stage_A(sm, A, row0, tid);
    #pragma unroll
    for (int jj = 0; jj < 32; jj++) {
        int idx = tid + jj * 512;
        int kp = idx >> 8, n = idx & 255;
        int k = kp * 2;
        float v0 = 0.f, v1 = 0.f;
        if (n < 188)      { v0 = Wlin[k * 188 + n]; v1 = Wlin[(k + 1) * 188 + n]; }
        else if (n >= 192 && n < 239) {
            int j = n - 192; v0 = Wskip[k * 47 + j]; v1 = Wskip[(k + 1) * 47 + j];
        }
        __nv_bfloat16 h0, l0, h1, l1;
        split_bf16(v0, h0, l0); split_bf16(v1, h1, l1);
        *(uint32_t*)(sm + SM_BHI + n * (BST * 2) + kp * 4) = pack_bf16(h0, h1);
        *(uint32_t*)(sm + SM_BLO + n * (BST * 2) + kp * 4) = pack_bf16(l0, l1);
    }
    __syncthreads();

    float acc[2][8][4];
    #pragma unroll
    for (int i = 0; i < 2; i++)
        #pragma unroll
        for (int j = 0; j < 8; j++)
            #pragma unroll
            for (int q = 0; q < 4; q++) acc[i][j][q] = 0.f;

    mma_mainloop(sm, acc, wid, lane);

    const int wm = wid >> 2, wn = wid & 3;
    const int g = lane >> 2, t = lane & 3;
    #pragma unroll
    for (int mt = 0; mt < 2; mt++) {
        #pragma unroll
        for (int half = 0; half < 2; half++) {
            int row = row0 + wm * 32 + mt * 16 + g + half * 8;
            if (row >= NN) continue;
            #pragma unroll
            for (int nt = 0; nt < 8; nt++) {
                #pragma unroll
                for (int q = 0; q < 2; q++) {
                    int c = wn * 64 + nt * 8 + t * 2 + q;
                    float v = acc[mt][nt][half * 2 + q];
                    if (c < 188)
                        Olin[(long long)row * 188 + c] = v;
                    else if (c >= 192 && c < 239)
                        Oskip[(long long)row * 47 + (c - 192)] = v;
                }
            }
        }
    }
}

// ---------------- per-node attention scores ----------------
__global__ void att_scores(const float* __restrict__ xh,
                           const float* __restrict__ ws,
                           const float* __restrict__ wd,
                           float* __restrict__ asrc, float* __restrict__ adst,
                           int C, int stride)
{
    int i = blockIdx.x * blockDim.x + threadIdx.x;
    if (i >= NN * 4) return;
    int node = i >> 2, h = i & 3;
    const float* row = xh + (long long)node * stride + h * C;
    const float* s_w = ws + h * C;
    const float* d_w = wd + h * C;
    float s1 = 0.f, s2 = 0.f;
    for (int c = 0; c < C; c++) {
        float v = row[c];
        s1 += v * s_w[c];
        s2 += v * d_w[c];
    }
    asrc[i] = s1;
    adst[i] = s2;
}

// ================= fused GAT aggregation (F=128) =================
__global__ __launch_bounds__(256) void gat_agg_128(
    const int* __restrict__ rowptr, const int* __restrict__ csr,
    const float* __restrict__ asrc, const float* __restrict__ adst,
    const float* __restrict__ xh, const float* __restrict__ skipb,
    const float* __restrict__ bias, const float* __restrict__ skip_b,
    float* __restrict__ xout)
{
    int w = (blockIdx.x * blockDim.x + threadIdx.x) >> 5;
    if (w >= NN) return;
    int lane = threadIdx.x & 31;
    int beg = rowptr[w], end = rowptr[w + 1];
    float4 ad = *(const float4*)(adst + 4 * w);

    float4 m = make_float4(-1e30f, -1e30f, -1e30f, -1e30f);
    for (int e = beg; e < end; e++) {
        int s = csr[e];
        float4 a = *(const float4*)(asrc + 4 * s);
        m.x = fmaxf(m.x, lrelu(a.x + ad.x));
        m.y = fmaxf(m.y, lrelu(a.y + ad.y));
        m.z = fmaxf(m.z, lrelu(a.z + ad.z));
        m.w = fmaxf(m.w, lrelu(a.w + ad.w));
    }

    int h = lane >> 3;
    float4 ws = make_float4(0.f, 0.f, 0.f, 0.f);
    float4 acc = make_float4(0.f, 0.f, 0.f, 0.f);
    for (int e = beg; e < end; e++) {
        int s = csr[e];
        float4 a = *(const float4*)(asrc + 4 * s);
        float wx = __expf(lrelu(a.x + ad.x) - m.x);
        float wy = __expf(lrelu(a.y + ad.y) - m.y);
        float wz = __expf(lrelu(a.z + ad.z) - m.z);
        float ww = __expf(lrelu(a.w + ad.w) - m.w);
        ws.x += wx; ws.y += wy; ws.z += wz; ws.w += ww;
        float wl = (h == 0) ? wx : (h == 1) ? wy : (h == 2) ? wz : ww;
        float4 v = *(const float4*)(xh + (long long)s * 128 + lane * 4);
        acc.x += wl * v.x; acc.y += wl * v.y; acc.z += wl * v.z; acc.w += wl * v.w;
    }
    float wsh = (h == 0) ? ws.x : (h == 1) ? ws.y : (h == 2) ? ws.z : ws.w;
    float inv = 1.f / (wsh + 1e-16f);

    int base = w * 128 + lane * 4;
    float4 sk = *(const float4*)(skipb + base);
    float4 bi = *(const float4*)(bias + lane * 4);
    float4 sb = *(const float4*)(skip_b + lane * 4);
    float4 o;
    o.x = acc.x * inv + sk.x + bi.x + sb.x;
    o.y = acc.y * inv + sk.y + bi.y + sb.y;
    o.z = acc.z * inv + sk.z + bi.z + sb.z;
    o.w = acc.w * inv + sk.w + bi.w + sb.w;
    o.x = o.x > 0.f ? o.x : expm1f(o.x);
    o.y = o.y > 0.f ? o.y : expm1f(o.y);
    o.z = o.z > 0.f ? o.z : expm1f(o.z);
    o.w = o.w > 0.f ? o.w : expm1f(o.w);
    *(float4*)(xout + base) = o;
}

// ================= fused GAT aggregation (layer 2, F=188, head-mean) ======
__global__ __launch_bounds__(256) void gat_agg_188(
    const int* __restrict__ rowptr, const int* __restrict__ csr,
    const float* __restrict__ asrc, const float* __restrict__ adst,
    const float* __restrict__ xh, const float* __restrict__ skipb,
    const float* __restrict__ bias2, const float* __restrict__ skip_b2,
    float* __restrict__ out)
{
    int w = (blockIdx.x * blockDim.x + threadIdx.x) >> 5;
    if (w >= NN) return;
    int lane = threadIdx.x & 31;
    int beg = rowptr[w], end = rowptr[w + 1];
    float4 ad = *(const float4*)(adst + 4 * w);

    float4 m = make_float4(-1e30f, -1e30f, -1e30f, -1e30f);
    for (int e = beg; e < end; e++) {
        int s = csr[e];
        float4 a = *(const float4*)(asrc + 4 * s);
        m.x = fmaxf(m.x, lrelu(a.x + ad.x));
        m.y = fmaxf(m.y, lrelu(a.y + ad.y));
        m.z = fmaxf(m.z, lrelu(a.z + ad.z));
        m.w = fmaxf(m.w, lrelu(a.w + ad.w));
    }

    float4 ws = make_float4(0.f, 0.f, 0.f, 0.f);
    float a00 = 0.f, a01 = 0.f, a02 = 0.f, a03 = 0.f;
    float a10 = 0.f, a11 = 0.f, a12 = 0.f, a13 = 0.f;
    int o1 = lane + 32;
    for (int e = beg; e < end; e++) {
        int s = csr[e];
        float4 a = *(const float4*)(asrc + 4 * s);
        float wx = __expf(lrelu(a.x + ad.x) - m.x);
        float wy = __expf(lrelu(a.y + ad.y) - m.y);
        float wz = __expf(lrelu(a.z + ad.z) - m.z);
        float ww = __expf(lrelu(a.w + ad.w) - m.w);
        ws.x += wx; ws.y += wy; ws.z += wz; ws.w += ww;
        const float* row = xh + (long long)s * 188;
        a00 += wx * row[lane];
        a01 += wy * row[47 + lane];
        a02 += wz * row[94 + lane];
        a03 += ww * row[141 + lane];
        if (o1 < 47) {
            a10 += wx * row[o1];
            a11 += wy * row[47 + o1];
            a12 += wz * row[94 + o1];
            a13 += ww * row[141 + o1];
        }
    }
    float ix = 1.f / (ws.x + 1e-16f);
    float iy = 1.f / (ws.y + 1e-16f);
    float iz = 1.f / (ws.z + 1e-16f);
    float iw = 1.f / (ws.w + 1e-16f);

    {
        int o = lane;
        float v = 0.25f * (a00 * ix + a01 * iy + a02 * iz + a03 * iw);
        out[w * 47 + o] = v + bias2[o] + skipb[w * 47 + o] + skip_b2[o];
    }
    if (o1 < 47) {
        float v = 0.25f * (a10 * ix + a11 * iy + a12 * iz + a13 * iw);
        out[w * 47 + o1] = v + bias2[o1] + skipb[w * 47 + o1] + skip_b2[o1];
    }
}

// ---------------- launch ----------------
extern "C" void kernel_launch(void* const* d_in, const int* in_sizes, int n_in,
                              void* d_out, int out_size)
{
    const float* x        = (const float*)d_in[0];
    const int*   ei       = (const int*)  d_in[1];
    const float* lin_w0   = (const float*)d_in[2];
    const float* att_src0 = (const float*)d_in[3];
    const float* att_dst0 = (const float*)d_in[4];
    const float* bias0    = (const float*)d_in[5];
    const float* skip_w0  = (const float*)d_in[6];
    const float* skip_b0  = (const float*)d_in[7];
    const float* lin_w1   = (const float*)d_in[8];
    const float* att_src1 = (const float*)d_in[9];
    const float* att_dst1 = (const float*)d_in[10];
    const float* bias1    = (const float*)d_in[11];
    const float* skip_w1  = (const float*)d_in[12];
    const float* skip_b1  = (const float*)d_in[13];
    const float* lin_w2   = (const float*)d_in[14];
    const float* att_src2 = (const float*)d_in[15];
    const float* att_dst2 = (const float*)d_in[16];
    const float* bias2    = (const float*)d_in[17];
    const float* skip_w2  = (const float*)d_in[18];
    const float* skip_b2  = (const float*)d_in[19];
    float* out = (float*)d_out;

    float *xh, *x1, *x2, *skipb, *asrc, *adst;
    int *deg, *ex, *bsum, *bpre, *rowptr, *cursor, *csr;
    cudaGetSymbolAddress((void**)&xh,     g_xh);
    cudaGetSymbolAddress((void**)&x1,     g_x1);
    cudaGetSymbolAddress((void**)&x2,     g_x2);
    cudaGetSymbolAddress((void**)&skipb,  g_skip);
    cudaGetSymbolAddress((void**)&asrc,   g_asrc);
    cudaGetSymbolAddress((void**)&adst,   g_adst);
    cudaGetSymbolAddress((void**)&deg,    g_deg);
    cudaGetSymbolAddress((void**)&ex,     g_ex);
    cudaGetSymbolAddress((void**)&bsum,   g_bsum);
    cudaGetSymbolAddress((void**)&bpre,   g_bpre);
    cudaGetSymbolAddress((void**)&rowptr, g_rowptr);
    cudaGetSymbolAddress((void**)&cursor, g_cursor);
    cudaGetSymbolAddress((void**)&csr,    g_csr);

    static int smem_set = 0;
    if (!smem_set) {
        cudaFuncSetAttribute(gemm_dual_128, cudaFuncAttributeMaxDynamicSharedMemorySize, SM_TOTAL);
        cudaFuncSetAttribute(gemm_l2,       cudaFuncAttributeMaxDynamicSharedMemorySize, SM_TOTAL);
        smem_set = 1;
    }

    const int GB   = (NN + 127) / 128;               // 391 GEMM row blocks
    const int EBLK = (ETOT + 255) / 256;             // 3321
    const int WGRD = (NN * 32 + 255) / 256;          // 6250 (warp per node)

    // ---------- CSR build (once, shared by all 3 layers) ----------
    cudaMemsetAsync(deg, 0, NN * sizeof(int));
    k_count<<<EBLK, 256>>>(ei, deg);
    k_scan1<<<NB_SCAN, 256>>>(deg, ex, bsum);
    k_scan2<<<1, 256>>>(bsum, bpre);
    k_scan3<<<(NN + 255) / 256, 256>>>(ex, bpre, rowptr, cursor);
    k_fill<<<EBLK, 256>>>(ei, cursor, csr);

    // ---------- layer 0 ----------
    gemm_dual_128<<<GB, 512, SM_TOTAL>>>(x, lin_w0, skip_w0, xh, skipb);
    att_scores<<<(NN * 4 + 255) / 256, 256>>>(xh, att_src0, att_dst0, asrc, adst, 32, 128);
    gat_agg_128<<<WGRD, 256>>>(rowptr, csr, asrc, adst, xh, skipb, bias0, skip_b0, x1);

    // ---------- layer 1 ----------
    gemm_dual_128<<<GB, 512, SM_TOTAL>>>(x1, lin_w1, skip_w1, xh, skipb);
    att_scores<<<(NN * 4 + 255) / 256, 256>>>(xh, att_src1, att_dst1, asrc, adst, 32, 128);
    gat_agg_128<<<WGRD, 256>>>(rowptr, csr, asrc, adst, xh, skipb, bias1, skip_b1, x2);

    // ---------- layer 2 ----------
    gemm_l2<<<GB, 512, SM_TOTAL>>>(x2, lin_w2, skip_w2, xh, skipb);
    att_scores<<<(NN * 4 + 255) / 256, 256>>>(xh, att_src2, att_dst2, asrc, adst, 47, 188);
    gat_agg_188<<<WGRD, 256>>>(rowptr, csr, asrc, adst, xh, skipb, bias2, skip_b2, out);
}

// round 10
// speedup vs baseline: 2.2508x; 1.2699x over previous
#include <cuda_runtime.h>
#include <cuda_bf16.h>
#include <cuda_fp16.h>
#include <math.h>
#include <stdint.h>

#define NN 50000
#define EE 800000
#define ETOT (EE + NN)
#define NB_SCAN 196   // ceil(50000/256)

// ---------------- scratch (no allocations allowed) ----------------
__device__ __align__(16) __half         g_xh_h[NN * 188];   // lin output, fp16
__device__ __align__(16) float          g_skip[NN * 128];   // skip GEMM output (fp32)
__device__ __align__(16) __nv_bfloat16  g_ahi [NN * 128];   // A image hi
__device__ __align__(16) __nv_bfloat16  g_alo [NN * 128];   // A image lo
__device__ __align__(16) __nv_bfloat16  g_wbhi[768 * 136];  // weight images (3 layers x 256 rows)
__device__ __align__(16) __nv_bfloat16  g_wblo[768 * 136];
__device__ float    g_asrc[NN * 4];
__device__ float    g_adst[NN * 4];
// CSR scratch
__device__ int      g_deg   [NN];
__device__ int      g_ex    [NN];
__device__ int      g_bsum  [256];
__device__ int      g_bpre  [256];
__device__ int      g_rowptr[NN + 1];
__device__ int      g_cursor[NN];
__device__ int      g_csr   [ETOT];

// ---------------- helpers ----------------
__device__ __forceinline__ float lrelu(float e) { return fmaxf(e, 0.2f * e); }

__device__ __forceinline__ uint32_t smem_u32(const void* p) {
    uint32_t a;
    asm("{ .reg .u64 t; cvta.to.shared.u64 t, %1; cvt.u32.u64 %0, t; }"
        : "=r"(a) : "l"(p));
    return a;
}

__device__ __forceinline__ void split_bf16(float v, __nv_bfloat16& h, __nv_bfloat16& l) {
    h = __float2bfloat16_rn(v);
    l = __float2bfloat16_rn(v - __bfloat162float(h));
}

__device__ __forceinline__ uint32_t pack_bf16(__nv_bfloat16 a, __nv_bfloat16 b) {
    return (uint32_t)__bfloat16_as_ushort(a) |
           ((uint32_t)__bfloat16_as_ushort(b) << 16);
}

__device__ __forceinline__ void ldsm_x4(uint32_t& r0, uint32_t& r1,
                                        uint32_t& r2, uint32_t& r3, uint32_t addr) {
    asm volatile("ldmatrix.sync.aligned.m8n8.x4.shared.b16 {%0,%1,%2,%3}, [%4];"
                 : "=r"(r0), "=r"(r1), "=r"(r2), "=r"(r3) : "r"(addr));
}

__device__ __forceinline__ void mma_bf16(float* c, const uint32_t* a, const uint32_t* b) {
    asm volatile(
        "mma.sync.aligned.m16n8k16.row.col.f32.bf16.bf16.f32 "
        "{%0,%1,%2,%3}, {%4,%5,%6,%7}, {%8,%9}, {%0,%1,%2,%3};"
        : "+f"(c[0]), "+f"(c[1]), "+f"(c[2]), "+f"(c[3])
        : "r"(a[0]), "r"(a[1]), "r"(a[2]), "r"(a[3]), "r"(b[0]), "r"(b[1]));
}

// SMEM layout (bytes), stride 136 bf16 = 272B per row
#define AST       136
#define BST       136
#define SM_AHI    0
#define SM_ALO    (128 * AST * 2)                 // 34816
#define SM_BHI    (SM_ALO + 128 * AST * 2)        // 69632
#define SM_BLO    (SM_BHI + 256 * BST * 2)        // 139264
#define SM_TOTAL  (SM_BLO + 256 * BST * 2)        // 208896

// ================= conversion kernels =================
// Weights -> bf16 hi/lo in the exact blocked smem image (row = n, stride 136)
__global__ void w_conv(const float* __restrict__ Wlin, const float* __restrict__ Wskip,
                       int Nlin, int Nskip, int skip_row0, int nrows,
                       __nv_bfloat16* __restrict__ whi, __nv_bfloat16* __restrict__ wlo)
{
    int idx = blockIdx.x * blockDim.x + threadIdx.x;
    if (idx >= nrows * 128) return;
    int n = idx >> 7, k = idx & 127;
    float v = 0.f;
    if (n < Nlin) v = Wlin[k * Nlin + n];
    else if (n >= skip_row0 && n - skip_row0 < Nskip) v = Wskip[k * Nskip + (n - skip_row0)];
    __nv_bfloat16 h, l;
    split_bf16(v, h, l);
    whi[n * 136 + k] = h;
    wlo[n * 136 + k] = l;
}

// x (fp32) -> A hi/lo image
__global__ void x_conv(const float* __restrict__ X,
                       __nv_bfloat16* __restrict__ hi, __nv_bfloat16* __restrict__ lo)
{
    int idx = blockIdx.x * blockDim.x + threadIdx.x;   // over NN*32 float4s
    if (idx >= NN * 32) return;
    float4 v = *(const float4*)(X + (long long)idx * 4);
    __nv_bfloat16 h0, l0, h1, l1, h2, l2, h3, l3;
    split_bf16(v.x, h0, l0); split_bf16(v.y, h1, l1);
    split_bf16(v.z, h2, l2); split_bf16(v.w, h3, l3);
    uint2 ph, pl;
    ph.x = pack_bf16(h0, h1); ph.y = pack_bf16(h2, h3);
    pl.x = pack_bf16(l0, l1); pl.y = pack_bf16(l2, l3);
    *(uint2*)((char*)hi + (long long)idx * 8) = ph;
    *(uint2*)((char*)lo + (long long)idx * 8) = pl;
}

// ================= CSR build =================
__global__ void k_count(const int* __restrict__ ei, int* __restrict__ deg) {
    int i = blockIdx.x * blockDim.x + threadIdx.x;
    if (i >= ETOT) return;
    int d = (i < EE) ? ei[EE + i] : i - EE;
    atomicAdd(&deg[d], 1);
}
__global__ void k_scan1(const int* __restrict__ deg, int* __restrict__ ex,
                        int* __restrict__ bsum) {
    __shared__ int sh[256];
    int t = threadIdx.x;
    int i = blockIdx.x * 256 + t;
    int v = (i < NN) ? deg[i] : 0;
    sh[t] = v;
    __syncthreads();
    for (int off = 1; off < 256; off <<= 1) {
        int a = (t >= off) ? sh[t - off] : 0;
        __syncthreads();
        sh[t] += a;
        __syncthreads();
    }
    if (i < NN) ex[i] = sh[t] - v;
    if (t == 255) bsum[blockIdx.x] = sh[255];
}
__global__ void k_scan2(const int* __restrict__ bsum, int* __restrict__ bpre) {
    __shared__ int sh[256];
    int t = threadIdx.x;
    int v = (t < NB_SCAN) ? bsum[t] : 0;
    sh[t] = v;
    __syncthreads();
    for (int off = 1; off < 256; off <<= 1) {
        int a = (t >= off) ? sh[t - off] : 0;
        __syncthreads();
        sh[t] += a;
        __syncthreads();
    }
    bpre[t] = sh[t] - v;
}
__global__ void k_scan3(const int* __restrict__ ex, const int* __restrict__ bpre,
                        int* __restrict__ rowptr, int* __restrict__ cursor) {
    int i = blockIdx.x * blockDim.x + threadIdx.x;
    if (i < NN) {
        int r = ex[i] + bpre[i >> 8];
        rowptr[i] = r;
        cursor[i] = r;
    }
    if (i == 0) rowptr[NN] = ETOT;
}
__global__ void k_fill(const int* __restrict__ ei, int* __restrict__ cursor,
                       int* __restrict__ csr) {
    int i = blockIdx.x * blockDim.x + threadIdx.x;
    if (i >= ETOT) return;
    int s, d;
    if (i < EE) { s = ei[i]; d = ei[EE + i]; } else { s = d = i - EE; }
    int pos = atomicAdd(&cursor[d], 1);
    csr[pos] = s;
}

// ============ staging (pure copies) + mma mainloop ============
__device__ __forceinline__ void stage_A2(char* sm, const __nv_bfloat16* __restrict__ ahi,
                                         const __nv_bfloat16* __restrict__ alo,
                                         int row0, int tid) {
    #pragma unroll
    for (int jj = 0; jj < 4; jj++) {
        int i = tid + jj * 512;          // 0..2047
        int r = i >> 4, q = i & 15;      // row, uint4 idx (16B)
        uint4 vh = make_uint4(0, 0, 0, 0), vl = make_uint4(0, 0, 0, 0);
        if (row0 + r < NN) {
            long long bofs = ((long long)(row0 + r) * 128 + q * 8) * 2;
            vh = *(const uint4*)((const char*)ahi + bofs);
            vl = *(const uint4*)((const char*)alo + bofs);
        }
        *(uint4*)(sm + SM_AHI + r * (AST * 2) + q * 16) = vh;
        *(uint4*)(sm + SM_ALO + r * (AST * 2) + q * 16) = vl;
    }
}

__device__ __forceinline__ void stage_B2(char* sm, const __nv_bfloat16* __restrict__ whi,
                                         const __nv_bfloat16* __restrict__ wlo, int tid) {
    // 256 rows x 272B = 69632B per array = 4352 uint4
    #pragma unroll
    for (int jj = 0; jj < 9; jj++) {
        int i = tid + jj * 512;
        if (i < 4352) {
            *(uint4*)(sm + SM_BHI + i * 16) = *(const uint4*)((const char*)whi + i * 16);
            *(uint4*)(sm + SM_BLO + i * 16) = *(const uint4*)((const char*)wlo + i * 16);
        }
    }
}

// mainloop: 8 k-steps, 3 passes; warp tile 32x64 (2 m-tiles x 8 n-tiles)
__device__ __forceinline__ void mma_mainloop(char* sm, float acc[2][8][4],
                                             int wid, int lane) {
    const uint32_t sb = smem_u32(sm);
    const int wm = wid >> 2, wn = wid & 3;
    const int m0r = wm * 32, n0 = wn * 64;
    const int ar = (lane & 15), ak = (lane >> 4) * 8;
    const int bn = ((lane >> 4) * 8) + (lane & 7);
    const int bk = ((lane >> 3) & 1) * 8;

    #pragma unroll
    for (int ks = 0; ks < 8; ks++) {
        int k0 = ks * 16;
        uint32_t ahi[2][4], alo[2][4], bhi[8][2], blo[8][2];
        #pragma unroll
        for (int mt = 0; mt < 2; mt++) {
            uint32_t addr = sb + SM_AHI + (m0r + mt * 16 + ar) * (AST * 2) + (k0 + ak) * 2;
            ldsm_x4(ahi[mt][0], ahi[mt][1], ahi[mt][2], ahi[mt][3], addr);
        }
        #pragma unroll
        for (int p = 0; p < 4; p++) {
            uint32_t addr = sb + SM_BHI + (n0 + p * 16 + bn) * (BST * 2) + (k0 + bk) * 2;
            ldsm_x4(bhi[2 * p][0], bhi[2 * p][1], bhi[2 * p + 1][0], bhi[2 * p + 1][1], addr);
        }
        #pragma unroll
        for (int mt = 0; mt < 2; mt++)
            #pragma unroll
            for (int nt = 0; nt < 8; nt++)
                mma_bf16(acc[mt][nt], ahi[mt], bhi[nt]);
        #pragma unroll
        for (int p = 0; p < 4; p++) {
            uint32_t addr = sb + SM_BLO + (n0 + p * 16 + bn) * (BST * 2) + (k0 + bk) * 2;
            ldsm_x4(blo[2 * p][0], blo[2 * p][1], blo[2 * p + 1][0], blo[2 * p + 1][1], addr);
        }
        #pragma unroll
        for (int mt = 0; mt < 2; mt++)
            #pragma unroll
            for (int nt = 0; nt < 8; nt++)
                mma_bf16(acc[mt][nt], ahi[mt], blo[nt]);
        #pragma unroll
        for (int mt = 0; mt < 2; mt++) {
            uint32_t addr = sb + SM_ALO + (m0r + mt * 16 + ar) * (AST * 2) + (k0 + ak) * 2;
            ldsm_x4(alo[mt][0], alo[mt][1], alo[mt][2], alo[mt][3], addr);
        }
        #pragma unroll
        for (int mt = 0; mt < 2; mt++)
            #pragma unroll
            for (int nt = 0; nt < 8; nt++)
                mma_bf16(acc[mt][nt], alo[mt], bhi[nt]);
    }
}

// ================= dual GEMM, layers 0/1 =================
// lin -> Xh (fp16, [N,128]); skip -> skipb (fp32, [N,128])
__global__ __launch_bounds__(512, 1) void gemm_dual_128(
    const __nv_bfloat16* __restrict__ ahi, const __nv_bfloat16* __restrict__ alo,
    const __nv_bfloat16* __restrict__ whi, const __nv_bfloat16* __restrict__ wlo,
    __half* __restrict__ Xh, float* __restrict__ Oskip)
{
    extern __shared__ char sm[];
    const int tid = threadIdx.x;
    const int wid = tid >> 5, lane = tid & 31;
    const int row0 = blockIdx.x << 7;

    stage_A2(sm, ahi, alo, row0, tid);
    stage_B2(sm, whi, wlo, tid);
    __syncthreads();

    float acc[2][8][4];
    #pragma unroll
    for (int i = 0; i < 2; i++)
        #pragma unroll
        for (int j = 0; j < 8; j++)
            #pragma unroll
            for (int q = 0; q < 4; q++) acc[i][j][q] = 0.f;

    mma_mainloop(sm, acc, wid, lane);

    const int wm = wid >> 2, wn = wid & 3;
    const int g = lane >> 2, t = lane & 3;
    #pragma unroll
    for (int mt = 0; mt < 2; mt++) {
        #pragma unroll
        for (int half_ = 0; half_ < 2; half_++) {
            int row = row0 + wm * 32 + mt * 16 + g + half_ * 8;
            if (row >= NN) continue;
            #pragma unroll
            for (int nt = 0; nt < 8; nt++) {
                int c = wn * 64 + nt * 8 + t * 2;
                float2 v = make_float2(acc[mt][nt][half_ * 2 + 0],
                                       acc[mt][nt][half_ * 2 + 1]);
                if (c < 128)
                    *(__half2*)(Xh + (long long)row * 128 + c) = __float22half2_rn(v);
                else
                    *(float2*)(Oskip + (long long)row * 128 + (c - 128)) = v;
            }
        }
    }
}

// ================= layer-2 GEMM (188 lin @0 fp16, 47 skip @192 fp32) ======
__global__ __launch_bounds__(512, 1) void gemm_l2(
    const __nv_bfloat16* __restrict__ ahi, const __nv_bfloat16* __restrict__ alo,
    const __nv_bfloat16* __restrict__ whi, const __nv_bfloat16* __restrict__ wlo,
    __half* __restrict__ Xh, float* __restrict__ Oskip)
{
    extern __shared__ char sm[];
    const int tid = threadIdx.x;
    const int wid = tid >> 5, lane = tid & 31;
    const int row0 = blockIdx.x << 7;

    stage_A2(sm, ahi, alo, row0, tid);
    stage_B2(sm, whi, wlo, tid);
    __syncthreads();

    float acc[2][8][4];
    #pragma unroll
    for (int i = 0; i < 2; i++)
        #pragma unroll
        for (int j = 0; j < 8; j++)
            #pragma unroll
            for (int q = 0; q < 4; q++) acc[i][j][q] = 0.f;

    mma_mainloop(sm, acc, wid, lane);

    const int wm = wid >> 2, wn = wid & 3;
    const int g = lane >> 2, t = lane & 3;
    #pragma unroll
    for (int mt = 0; mt < 2; mt++) {
        #pragma unroll
        for (int half_ = 0; half_ < 2; half_++) {
            int row = row0 + wm * 32 + mt * 16 + g + half_ * 8;
            if (row >= NN) continue;
            #pragma unroll
            for (int nt = 0; nt < 8; nt++) {
                int c = wn * 64 + nt * 8 + t * 2;
                float2 v = make_float2(acc[mt][nt][half_ * 2 + 0],
                                       acc[mt][nt][half_ * 2 + 1]);
                if (c < 188) {
                    *(__half2*)(Xh + (long long)row * 188 + c) = __float22half2_rn(v);
                } else {
                    #pragma unroll
                    for (int q = 0; q < 2; q++) {
                        int cc = c + q;
                        if (cc >= 192 && cc < 239)
                            Oskip[(long long)row * 47 + (cc - 192)] = (q ? v.y : v.x);
                    }
                }
            }
        }
    }
}

// ---------------- per-node attention scores (fp16 xh) ----------------
__global__ void att_scores(const __half* __restrict__ xh,
                           const float* __restrict__ ws,
                           const float* __restrict__ wd,
                           float* __restrict__ asrc, float* __restrict__ adst,
                           int C, int stride)
{
    int i = blockIdx.x * blockDim.x + threadIdx.x;
    if (i >= NN * 4) return;
    int node = i >> 2, h = i & 3;
    const __half* row = xh + (long long)node * stride + h * C;
    const float* s_w = ws + h * C;
    const float* d_w = wd + h * C;
    float s1 = 0.f, s2 = 0.f;
    for (int c = 0; c < C; c++) {
        float v = __half2float(row[c]);
        s1 += v * s_w[c];
        s2 += v * d_w[c];
    }
    asrc[i] = s1;
    adst[i] = s2;
}

// ================= fused GAT aggregation (F=128), single-pass =============
// unshifted exp (scores bounded, fp32 safe); epilogue writes bf16 hi/lo A image
__global__ __launch_bounds__(256) void gat_agg_128(
    const int* __restrict__ rowptr, const int* __restrict__ csr,
    const float* __restrict__ asrc, const float* __restrict__ adst,
    const __half* __restrict__ xh, const float* __restrict__ skipb,
    const float* __restrict__ bias, const float* __restrict__ skip_b,
    __nv_bfloat16* __restrict__ ahi, __nv_bfloat16* __restrict__ alo)
{
    int w = (blockIdx.x * blockDim.x + threadIdx.x) >> 5;
    if (w >= NN) return;
    int lane = threadIdx.x & 31;
    int beg = rowptr[w], end = rowptr[w + 1];
    float4 ad = *(const float4*)(adst + 4 * w);

    int h = lane >> 3;
    float4 s4 = make_float4(0.f, 0.f, 0.f, 0.f);
    float4 acc = make_float4(0.f, 0.f, 0.f, 0.f);
    for (int e = beg; e < end; e++) {
        int s = csr[e];
        float4 a = *(const float4*)(asrc + 4 * s);
        float wx = __expf(lrelu(a.x + ad.x));
        float wy = __expf(lrelu(a.y + ad.y));
        float wz = __expf(lrelu(a.z + ad.z));
        float ww = __expf(lrelu(a.w + ad.w));
        s4.x += wx; s4.y += wy; s4.z += wz; s4.w += ww;
        float wl = (h == 0) ? wx : (h == 1) ? wy : (h == 2) ? wz : ww;
        uint2 raw = *(const uint2*)(xh + (long long)s * 128 + lane * 4);
        float2 p0 = __half22float2(*(const __half2*)&raw.x);
        float2 p1 = __half22float2(*(const __half2*)&raw.y);
        acc.x += wl * p0.x; acc.y += wl * p0.y;
        acc.z += wl * p1.x; acc.w += wl * p1.y;
    }
    float wsh = (h == 0) ? s4.x : (h == 1) ? s4.y : (h == 2) ? s4.z : s4.w;
    float inv = 1.f / (wsh + 1e-16f);

    int base = w * 128 + lane * 4;
    float4 sk = *(const float4*)(skipb + base);
    float4 bi = *(const float4*)(bias + lane * 4);
    float4 sb = *(const float4*)(skip_b + lane * 4);
    float4 o;
    o.x = acc.x * inv + sk.x + bi.x + sb.x;
    o.y = acc.y * inv + sk.y + bi.y + sb.y;
    o.z = acc.z * inv + sk.z + bi.z + sb.z;
    o.w = acc.w * inv + sk.w + bi.w + sb.w;
    o.x = o.x > 0.f ? o.x : expm1f(o.x);
    o.y = o.y > 0.f ? o.y : expm1f(o.y);
    o.z = o.z > 0.f ? o.z : expm1f(o.z);
    o.w = o.w > 0.f ? o.w : expm1f(o.w);

    __nv_bfloat16 h0, l0, h1, l1, h2, l2, h3, l3;
    split_bf16(o.x, h0, l0); split_bf16(o.y, h1, l1);
    split_bf16(o.z, h2, l2); split_bf16(o.w, h3, l3);
    uint2 ph, pl;
    ph.x = pack_bf16(h0, h1); ph.y = pack_bf16(h2, h3);
    pl.x = pack_bf16(l0, l1); pl.y = pack_bf16(l2, l3);
    *(uint2*)((char*)ahi + (long long)base * 2) = ph;
    *(uint2*)((char*)alo + (long long)base * 2) = pl;
}

// ================= fused GAT aggregation (layer 2, head-mean) =============
__global__ __launch_bounds__(256) void gat_agg_188(
    const int* __restrict__ rowptr, const int* __restrict__ csr,
    const float* __restrict__ asrc, const float* __restrict__ adst,
    const __half* __restrict__ xh, const float* __restrict__ skipb,
    const float* __restrict__ bias2, const float* __restrict__ skip_b2,
    float* __restrict__ out)
{
    int w = (blockIdx.x * blockDim.x + threadIdx.x) >> 5;
    if (w >= NN) return;
    int lane = threadIdx.x & 31;
    int beg = rowptr[w], end = rowptr[w + 1];
    float4 ad = *(const float4*)(adst + 4 * w);

    float4 s4 = make_float4(0.f, 0.f, 0.f, 0.f);
    float a00 = 0.f, a01 = 0.f, a02 = 0.f, a03 = 0.f;
    float a10 = 0.f, a11 = 0.f, a12 = 0.f, a13 = 0.f;
    int o1 = lane + 32;
    for (int e = beg; e < end; e++) {
        int s = csr[e];
        float4 a = *(const float4*)(asrc + 4 * s);
        float wx = __expf(lrelu(a.x + ad.x));
        float wy = __expf(lrelu(a.y + ad.y));
        float wz = __expf(lrelu(a.z + ad.z));
        float ww = __expf(lrelu(a.w + ad.w));
        s4.x += wx; s4.y += wy; s4.z += wz; s4.w += ww;
        const __half* row = xh + (long long)s * 188;
        a00 += wx * __half2float(row[lane]);
        a01 += wy * __half2float(row[47 + lane]);
        a02 += wz * __half2float(row[94 + lane]);
        a03 += ww * __half2float(row[141 + lane]);
        if (o1 < 47) {
            a10 += wx * __half2float(row[o1]);
            a11 += wy * __half2float(row[47 + o1]);
            a12 += wz * __half2float(row[94 + o1]);
            a13 += ww * __half2float(row[141 + o1]);
        }
    }
    float ix = 1.f / (s4.x + 1e-16f);
    float iy = 1.f / (s4.y + 1e-16f);
    float iz = 1.f / (s4.z + 1e-16f);
    float iw = 1.f / (s4.w + 1e-16f);

    {
        int o = lane;
        float v = 0.25f * (a00 * ix + a01 * iy + a02 * iz + a03 * iw);
        out[w * 47 + o] = v + bias2[o] + skipb[w * 47 + o] + skip_b2[o];
    }
    if (o1 < 47) {
        float v = 0.25f * (a10 * ix + a11 * iy + a12 * iz + a13 * iw);
        out[w * 47 + o1] = v + bias2[o1] + skipb[w * 47 + o1] + skip_b2[o1];
    }
}

// ---------------- launch ----------------
extern "C" void kernel_launch(void* const* d_in, const int* in_sizes, int n_in,
                              void* d_out, int out_size)
{
    const float* x        = (const float*)d_in[0];
    const int*   ei       = (const int*)  d_in[1];
    const float* lin_w0   = (const float*)d_in[2];
    const float* att_src0 = (const float*)d_in[3];
    const float* att_dst0 = (const float*)d_in[4];
    const float* bias0    = (const float*)d_in[5];
    const float* skip_w0  = (const float*)d_in[6];
    const float* skip_b0  = (const float*)d_in[7];
    const float* lin_w1   = (const float*)d_in[8];
    const float* att_src1 = (const float*)d_in[9];
    const float* att_dst1 = (const float*)d_in[10];
    const float* bias1    = (const float*)d_in[11];
    const float* skip_w1  = (const float*)d_in[12];
    const float* skip_b1  = (const float*)d_in[13];
    const float* lin_w2   = (const float*)d_in[14];
    const float* att_src2 = (const float*)d_in[15];
    const float* att_dst2 = (const float*)d_in[16];
    const float* bias2    = (const float*)d_in[17];
    const float* skip_w2  = (const float*)d_in[18];
    const float* skip_b2  = (const float*)d_in[19];
    float* out = (float*)d_out;

    __half* xh_h; float *skipb, *asrc, *adst;
    __nv_bfloat16 *ahi, *alo, *wbhi, *wblo;
    int *deg, *ex, *bsum, *bpre, *rowptr, *cursor, *csr;
    cudaGetSymbolAddress((void**)&xh_h,   g_xh_h);
    cudaGetSymbolAddress((void**)&skipb,  g_skip);
    cudaGetSymbolAddress((void**)&ahi,    g_ahi);
    cudaGetSymbolAddress((void**)&alo,    g_alo);
    cudaGetSymbolAddress((void**)&wbhi,   g_wbhi);
    cudaGetSymbolAddress((void**)&wblo,   g_wblo);
    cudaGetSymbolAddress((void**)&asrc,   g_asrc);
    cudaGetSymbolAddress((void**)&adst,   g_adst);
    cudaGetSymbolAddress((void**)&deg,    g_deg);
    cudaGetSymbolAddress((void**)&ex,     g_ex);
    cudaGetSymbolAddress((void**)&bsum,   g_bsum);
    cudaGetSymbolAddress((void**)&bpre,   g_bpre);
    cudaGetSymbolAddress((void**)&rowptr, g_rowptr);
    cudaGetSymbolAddress((void**)&cursor, g_cursor);
    cudaGetSymbolAddress((void**)&csr,    g_csr);

    static int smem_set = 0;
    if (!smem_set) {
        cudaFuncSetAttribute(gemm_dual_128, cudaFuncAttributeMaxDynamicSharedMemorySize, SM_TOTAL);
        cudaFuncSetAttribute(gemm_l2,       cudaFuncAttributeMaxDynamicSharedMemorySize, SM_TOTAL);
        smem_set = 1;
    }

    const int GB   = (NN + 127) / 128;               // 391 GEMM row blocks
    const int EBLK = (ETOT + 255) / 256;             // 3321
    const int WGRD = (NN * 32 + 255) / 256;          // 6250 (warp per node)

    // ---------- conversions (weights + x) ----------
    w_conv<<<(256 * 128 + 255) / 256, 256>>>(lin_w0, skip_w0, 128, 128, 128, 256,
                                             wbhi, wblo);
    w_conv<<<(256 * 128 + 255) / 256, 256>>>(lin_w1, skip_w1, 128, 128, 128, 256,
                                             wbhi + 256 * 136, wblo + 256 * 136);
    w_conv<<<(240 * 128 + 255) / 256, 256>>>(lin_w2, skip_w2, 188, 47, 192, 240,
                                             wbhi + 512 * 136, wblo + 512 * 136);
    x_conv<<<(NN * 32 + 255) / 256, 256>>>(x, ahi, alo);

    // ---------- CSR build (once, shared by all 3 layers) ----------
    cudaMemsetAsync(deg, 0, NN * sizeof(int));
    k_count<<<EBLK, 256>>>(ei, deg);
    k_scan1<<<NB_SCAN, 256>>>(deg, ex, bsum);
    k_scan2<<<1, 256>>>(bsum, bpre);
    k_scan3<<<(NN + 255) / 256, 256>>>(ex, bpre, rowptr, cursor);
    k_fill<<<EBLK, 256>>>(ei, cursor, csr);

    // ---------- layer 0 ----------
    gemm_dual_128<<<GB, 512, SM_TOTAL>>>(ahi, alo, wbhi, wblo, xh_h, skipb);
    att_scores<<<(NN * 4 + 255) / 256, 256>>>(xh_h, att_src0, att_dst0, asrc, adst, 32, 128);
    gat_agg_128<<<WGRD, 256>>>(rowptr, csr, asrc, adst, xh_h, skipb, bias0, skip_b0, ahi, alo);

    // ---------- layer 1 ----------
    gemm_dual_128<<<GB, 512, SM_TOTAL>>>(ahi, alo, wbhi + 256 * 136, wblo + 256 * 136, xh_h, skipb);
    att_scores<<<(NN * 4 + 255) / 256, 256>>>(xh_h, att_src1, att_dst1, asrc, adst, 32, 128);
    gat_agg_128<<<WGRD, 256>>>(rowptr, csr, asrc, adst, xh_h, skipb, bias1, skip_b1, ahi, alo);

    // ---------- layer 2 ----------
    gemm_l2<<<GB, 512, SM_TOTAL>>>(ahi, alo, wbhi + 512 * 136, wblo + 512 * 136, xh_h, skipb);
    att_scores<<<(NN * 4 + 255) / 256, 256>>>(xh_h, att_src2, att_dst2, asrc, adst, 47, 188);
    gat_agg_188<<<WGRD, 256>>>(rowptr, csr, asrc, adst, xh_h, skipb, bias2, skip_b2, out);
}

// round 11
// speedup vs baseline: 2.4646x; 1.0950x over previous
#include <cuda_runtime.h>
#include <cuda_bf16.h>
#include <cuda_fp16.h>
#include <math.h>
#include <stdint.h>

#define NN 50000
#define EE 800000
#define ETOT (EE + NN)
#define NB_SCAN 196   // ceil(50000/256)

// ---------------- scratch (no allocations allowed) ----------------
__device__ __align__(16) __half         g_xh_h[NN * 188];   // lin output, fp16
__device__ __align__(16) float          g_skip[NN * 128];   // skip GEMM output (fp32)
__device__ __align__(16) __nv_bfloat16  g_ahi [NN * 128];   // A image hi
__device__ __align__(16) __nv_bfloat16  g_alo [NN * 128];   // A image lo
__device__ __align__(16) __nv_bfloat16  g_wbhi[768 * 136];  // weight images (3 layers)
__device__ __align__(16) __nv_bfloat16  g_wblo[768 * 136];
__device__ float    g_asrc[NN * 4];
__device__ float    g_adst[NN * 4];
// CSR scratch
__device__ int      g_deg   [NN];
__device__ int      g_ex    [NN];
__device__ int      g_bsum  [256];
__device__ int      g_rowptr[NN + 1];
__device__ int      g_cursor[NN];
__device__ int      g_csr   [ETOT];

// ---------------- helpers ----------------
__device__ __forceinline__ float lrelu(float e) { return fmaxf(e, 0.2f * e); }

__device__ __forceinline__ uint32_t smem_u32(const void* p) {
    uint32_t a;
    asm("{ .reg .u64 t; cvta.to.shared.u64 t, %1; cvt.u32.u64 %0, t; }"
        : "=r"(a) : "l"(p));
    return a;
}

__device__ __forceinline__ void split_bf16(float v, __nv_bfloat16& h, __nv_bfloat16& l) {
    h = __float2bfloat16_rn(v);
    l = __float2bfloat16_rn(v - __bfloat162float(h));
}

__device__ __forceinline__ uint32_t pack_bf16(__nv_bfloat16 a, __nv_bfloat16 b) {
    return (uint32_t)__bfloat16_as_ushort(a) |
           ((uint32_t)__bfloat16_as_ushort(b) << 16);
}

__device__ __forceinline__ void ldsm_x4(uint32_t& r0, uint32_t& r1,
                                        uint32_t& r2, uint32_t& r3, uint32_t addr) {
    asm volatile("ldmatrix.sync.aligned.m8n8.x4.shared.b16 {%0,%1,%2,%3}, [%4];"
                 : "=r"(r0), "=r"(r1), "=r"(r2), "=r"(r3) : "r"(addr));
}

__device__ __forceinline__ void mma_bf16(float* c, const uint32_t* a, const uint32_t* b) {
    asm volatile(
        "mma.sync.aligned.m16n8k16.row.col.f32.bf16.bf16.f32 "
        "{%0,%1,%2,%3}, {%4,%5,%6,%7}, {%8,%9}, {%0,%1,%2,%3};"
        : "+f"(c[0]), "+f"(c[1]), "+f"(c[2]), "+f"(c[3])
        : "r"(a[0]), "r"(a[1]), "r"(a[2]), "r"(a[3]), "r"(b[0]), "r"(b[1]));
}

// SMEM layout (bytes), stride 136 bf16 = 272B per row
#define AST       136
#define BST       136
#define SM_AHI    0
#define SM_ALO    (128 * AST * 2)                 // 34816
#define SM_BHI    (SM_ALO + 128 * AST * 2)        // 69632
#define SM_BLO    (SM_BHI + 256 * BST * 2)        // 139264
#define SM_TOTAL  (SM_BLO + 256 * BST * 2)        // 208896

// ================= merged conversion kernel =================
// blocks [0,384): weight images (3 layers, 768 rows x 128 k)
// blocks [384, 384+6250): x -> A hi/lo image
__global__ void conv_all(
    const float* __restrict__ w0l, const float* __restrict__ w0s,
    const float* __restrict__ w1l, const float* __restrict__ w1s,
    const float* __restrict__ w2l, const float* __restrict__ w2s,
    const float* __restrict__ X,
    __nv_bfloat16* __restrict__ whi, __nv_bfloat16* __restrict__ wlo,
    __nv_bfloat16* __restrict__ ahi, __nv_bfloat16* __restrict__ alo)
{
    int bx = blockIdx.x;
    if (bx < 384) {
        int idx = bx * 256 + threadIdx.x;          // over 768*128
        int n = idx >> 7, k = idx & 127;
        int layer = n >> 8, nl = n & 255;
        float v = 0.f;
        if (layer == 0) {
            v = (nl < 128) ? w0l[k * 128 + nl] : w0s[k * 128 + (nl - 128)];
        } else if (layer == 1) {
            v = (nl < 128) ? w1l[k * 128 + nl] : w1s[k * 128 + (nl - 128)];
        } else {
            if (nl < 188) v = w2l[k * 188 + nl];
            else if (nl >= 192 && nl < 239) v = w2s[k * 47 + (nl - 192)];
        }
        __nv_bfloat16 h, l;
        split_bf16(v, h, l);
        whi[n * 136 + k] = h;
        wlo[n * 136 + k] = l;
    } else {
        int idx = (bx - 384) * 256 + threadIdx.x;  // over NN*32 float4s
        if (idx >= NN * 32) return;
        float4 v = *(const float4*)(X + (long long)idx * 4);
        __nv_bfloat16 h0, l0, h1, l1, h2, l2, h3, l3;
        split_bf16(v.x, h0, l0); split_bf16(v.y, h1, l1);
        split_bf16(v.z, h2, l2); split_bf16(v.w, h3, l3);
        uint2 ph, pl;
        ph.x = pack_bf16(h0, h1); ph.y = pack_bf16(h2, h3);
        pl.x = pack_bf16(l0, l1); pl.y = pack_bf16(l2, l3);
        *(uint2*)((char*)ahi + (long long)idx * 8) = ph;
        *(uint2*)((char*)alo + (long long)idx * 8) = pl;
    }
}

// ================= CSR build =================
__global__ void k_count(const int* __restrict__ ei, int* __restrict__ deg) {
    int i = blockIdx.x * blockDim.x + threadIdx.x;
    if (i >= ETOT) return;
    int d = (i < EE) ? ei[EE + i] : i - EE;
    atomicAdd(&deg[d], 1);
}
__global__ void k_scan1(const int* __restrict__ deg, int* __restrict__ ex,
                        int* __restrict__ bsum) {
    __shared__ int sh[256];
    int t = threadIdx.x;
    int i = blockIdx.x * 256 + t;
    int v = (i < NN) ? deg[i] : 0;
    sh[t] = v;
    __syncthreads();
    for (int off = 1; off < 256; off <<= 1) {
        int a = (t >= off) ? sh[t - off] : 0;
        __syncthreads();
        sh[t] += a;
        __syncthreads();
    }
    if (i < NN) ex[i] = sh[t] - v;
    if (t == 255) bsum[blockIdx.x] = sh[255];
}
// merged scan2+scan3: each block locally reduces bsum[0..bid)
__global__ void k_scan23(const int* __restrict__ ex, const int* __restrict__ bsum,
                         int* __restrict__ rowptr, int* __restrict__ cursor) {
    __shared__ int sh[256];
    int t = threadIdx.x, b = blockIdx.x;
    sh[t] = (t < b) ? bsum[t] : 0;     // b <= 195 < 256
    __syncthreads();
    for (int off = 128; off; off >>= 1) {
        if (t < off) sh[t] += sh[t + off];
        __syncthreads();
    }
    int bpre = sh[0];
    int i = b * 256 + t;
    if (i < NN) {
        int r = ex[i] + bpre;
        rowptr[i] = r;
        cursor[i] = r;
    }
    if (i == 0) rowptr[NN] = ETOT;
}
__global__ void k_fill(const int* __restrict__ ei, int* __restrict__ cursor,
                       int* __restrict__ csr) {
    int i = blockIdx.x * blockDim.x + threadIdx.x;
    if (i >= ETOT) return;
    int s, d;
    if (i < EE) { s = ei[i]; d = ei[EE + i]; } else { s = d = i - EE; }
    int pos = atomicAdd(&cursor[d], 1);
    csr[pos] = s;
}

// ============ staging (pure copies) + mma mainloop ============
__device__ __forceinline__ void stage_A2(char* sm, const __nv_bfloat16* __restrict__ ahi,
                                         const __nv_bfloat16* __restrict__ alo,
                                         int row0, int tid) {
    #pragma unroll
    for (int jj = 0; jj < 4; jj++) {
        int i = tid + jj * 512;          // 0..2047
        int r = i >> 4, q = i & 15;      // row, uint4 idx (16B)
        uint4 vh = make_uint4(0, 0, 0, 0), vl = make_uint4(0, 0, 0, 0);
        if (row0 + r < NN) {
            long long bofs = ((long long)(row0 + r) * 128 + q * 8) * 2;
            vh = *(const uint4*)((const char*)ahi + bofs);
            vl = *(const uint4*)((const char*)alo + bofs);
        }
        *(uint4*)(sm + SM_AHI + r * (AST * 2) + q * 16) = vh;
        *(uint4*)(sm + SM_ALO + r * (AST * 2) + q * 16) = vl;
    }
}

__device__ __forceinline__ void stage_B2(char* sm, const __nv_bfloat16* __restrict__ whi,
                                         const __nv_bfloat16* __restrict__ wlo, int tid) {
    // 256 rows x 272B = 69632B per array = 4352 uint4
    #pragma unroll
    for (int jj = 0; jj < 9; jj++) {
        int i = tid + jj * 512;
        if (i < 4352) {
            *(uint4*)(sm + SM_BHI + i * 16) = *(const uint4*)((const char*)whi + i * 16);
            *(uint4*)(sm + SM_BLO + i * 16) = *(const uint4*)((const char*)wlo + i * 16);
        }
    }
}

// mainloop: 8 k-steps, 3 passes; warp tile 32x64 (2 m-tiles x 8 n-tiles)
__device__ __forceinline__ void mma_mainloop(char* sm, float acc[2][8][4],
                                             int wid, int lane) {
    const uint32_t sb = smem_u32(sm);
    const int wm = wid >> 2, wn = wid & 3;
    const int m0r = wm * 32, n0 = wn * 64;
    const int ar = (lane & 15), ak = (lane >> 4) * 8;
    const int bn = ((lane >> 4) * 8) + (lane & 7);
    const int bk = ((lane >> 3) & 1) * 8;

    #pragma unroll
    for (int ks = 0; ks < 8; ks++) {
        int k0 = ks * 16;
        uint32_t ahi[2][4], alo[2][4], bhi[8][2], blo[8][2];
        #pragma unroll
        for (int mt = 0; mt < 2; mt++) {
            uint32_t addr = sb + SM_AHI + (m0r + mt * 16 + ar) * (AST * 2) + (k0 + ak) * 2;
            ldsm_x4(ahi[mt][0], ahi[mt][1], ahi[mt][2], ahi[mt][3], addr);
        }
        #pragma unroll
        for (int p = 0; p < 4; p++) {
            uint32_t addr = sb + SM_BHI + (n0 + p * 16 + bn) * (BST * 2) + (k0 + bk) * 2;
            ldsm_x4(bhi[2 * p][0], bhi[2 * p][1], bhi[2 * p + 1][0], bhi[2 * p + 1][1], addr);
        }
        #pragma unroll
        for (int mt = 0; mt < 2; mt++)
            #pragma unroll
            for (int nt = 0; nt < 8; nt++)
                mma_bf16(acc[mt][nt], ahi[mt], bhi[nt]);
        #pragma unroll
        for (int p = 0; p < 4; p++) {
            uint32_t addr = sb + SM_BLO + (n0 + p * 16 + bn) * (BST * 2) + (k0 + bk) * 2;
            ldsm_x4(blo[2 * p][0], blo[2 * p][1], blo[2 * p + 1][0], blo[2 * p + 1][1], addr);
        }
        #pragma unroll
        for (int mt = 0; mt < 2; mt++)
            #pragma unroll
            for (int nt = 0; nt < 8; nt++)
                mma_bf16(acc[mt][nt], ahi[mt], blo[nt]);
        #pragma unroll
        for (int mt = 0; mt < 2; mt++) {
            uint32_t addr = sb + SM_ALO + (m0r + mt * 16 + ar) * (AST * 2) + (k0 + ak) * 2;
            ldsm_x4(alo[mt][0], alo[mt][1], alo[mt][2], alo[mt][3], addr);
        }
        #pragma unroll
        for (int mt = 0; mt < 2; mt++)
            #pragma unroll
            for (int nt = 0; nt < 8; nt++)
                mma_bf16(acc[mt][nt], alo[mt], bhi[nt]);
    }
}

// ================= dual GEMM, layers 0/1 + fused attention scores =========
// lin -> Xh (fp16); skip -> skipb (fp32); asrc/adst from fp32 accumulators.
__global__ __launch_bounds__(512, 1) void gemm_dual_128(
    const __nv_bfloat16* __restrict__ ahi, const __nv_bfloat16* __restrict__ alo,
    const __nv_bfloat16* __restrict__ whi, const __nv_bfloat16* __restrict__ wlo,
    const float* __restrict__ AttS, const float* __restrict__ AttD,
    __half* __restrict__ Xh, float* __restrict__ Oskip,
    float* __restrict__ asrc, float* __restrict__ adst)
{
    extern __shared__ char sm[];
    const int tid = threadIdx.x;
    const int wid = tid >> 5, lane = tid & 31;
    const int row0 = blockIdx.x << 7;

    stage_A2(sm, ahi, alo, row0, tid);
    stage_B2(sm, whi, wlo, tid);
    __syncthreads();

    float acc[2][8][4];
    #pragma unroll
    for (int i = 0; i < 2; i++)
        #pragma unroll
        for (int j = 0; j < 8; j++)
            #pragma unroll
            for (int q = 0; q < 4; q++) acc[i][j][q] = 0.f;

    mma_mainloop(sm, acc, wid, lane);

    const int wm = wid >> 2, wn = wid & 3;
    const int g = lane >> 2, t = lane & 3;

    // store lin/skip outputs
    #pragma unroll
    for (int mt = 0; mt < 2; mt++) {
        #pragma unroll
        for (int half_ = 0; half_ < 2; half_++) {
            int row = row0 + wm * 32 + mt * 16 + g + half_ * 8;
            if (row >= NN) continue;
            #pragma unroll
            for (int nt = 0; nt < 8; nt++) {
                int c = wn * 64 + nt * 8 + t * 2;
                float2 v = make_float2(acc[mt][nt][half_ * 2 + 0],
                                       acc[mt][nt][half_ * 2 + 1]);
                if (c < 128)
                    *(__half2*)(Xh + (long long)row * 128 + c) = __float22half2_rn(v);
                else
                    *(float2*)(Oskip + (long long)row * 128 + (c - 128)) = v;
            }
        }
    }

    // fused attention scores (lin cols live in warps wn<2; head = 2wn + (nt>=4))
    if (wn < 2) {
        #pragma unroll
        for (int mt = 0; mt < 2; mt++) {
            #pragma unroll
            for (int half_ = 0; half_ < 2; half_++) {
                float ps0 = 0.f, ps1 = 0.f, pd0 = 0.f, pd1 = 0.f;
                #pragma unroll
                for (int nt = 0; nt < 8; nt++) {
                    #pragma unroll
                    for (int q = 0; q < 2; q++) {
                        int c = wn * 64 + nt * 8 + t * 2 + q;
                        float v = acc[mt][nt][half_ * 2 + q];
                        float cs = AttS[c], cd = AttD[c];
                        if (nt < 4) { ps0 += v * cs; pd0 += v * cd; }
                        else        { ps1 += v * cs; pd1 += v * cd; }
                    }
                }
                ps0 += __shfl_xor_sync(0xFFFFFFFFu, ps0, 1);
                ps0 += __shfl_xor_sync(0xFFFFFFFFu, ps0, 2);
                ps1 += __shfl_xor_sync(0xFFFFFFFFu, ps1, 1);
                ps1 += __shfl_xor_sync(0xFFFFFFFFu, ps1, 2);
                pd0 += __shfl_xor_sync(0xFFFFFFFFu, pd0, 1);
                pd0 += __shfl_xor_sync(0xFFFFFFFFu, pd0, 2);
                pd1 += __shfl_xor_sync(0xFFFFFFFFu, pd1, 1);
                pd1 += __shfl_xor_sync(0xFFFFFFFFu, pd1, 2);
                int row = row0 + wm * 32 + mt * 16 + g + half_ * 8;
                if (t == 0 && row < NN) {
                    int h0 = wn * 2, h1 = wn * 2 + 1;
                    asrc[row * 4 + h0] = ps0;
                    asrc[row * 4 + h1] = ps1;
                    adst[row * 4 + h0] = pd0;
                    adst[row * 4 + h1] = pd1;
                }
            }
        }
    }
}

// ================= layer-2 GEMM (188 lin @0 fp16, 47 skip @192 fp32) ======
__global__ __launch_bounds__(512, 1) void gemm_l2(
    const __nv_bfloat16* __restrict__ ahi, const __nv_bfloat16* __restrict__ alo,
    const __nv_bfloat16* __restrict__ whi, const __nv_bfloat16* __restrict__ wlo,
    __half* __restrict__ Xh, float* __restrict__ Oskip)
{
    extern __shared__ char sm[];
    const int tid = threadIdx.x;
    const int wid = tid >> 5, lane = tid & 31;
    const int row0 = blockIdx.x << 7;

    stage_A2(sm, ahi, alo, row0, tid);
    stage_B2(sm, whi, wlo, tid);
    __syncthreads();

    float acc[2][8][4];
    #pragma unroll
    for (int i = 0; i < 2; i++)
        #pragma unroll
        for (int j = 0; j < 8; j++)
            #pragma unroll
            for (int q = 0; q < 4; q++) acc[i][j][q] = 0.f;

    mma_mainloop(sm, acc, wid, lane);

    const int wm = wid >> 2, wn = wid & 3;
    const int g = lane >> 2, t = lane & 3;
    #pragma unroll
    for (int mt = 0; mt < 2; mt++) {
        #pragma unroll
        for (int half_ = 0; half_ < 2; half_++) {
            int row = row0 + wm * 32 + mt * 16 + g + half_ * 8;
            if (row >= NN) continue;
            #pragma unroll
            for (int nt = 0; nt < 8; nt++) {
                int c = wn * 64 + nt * 8 + t * 2;
                float2 v = make_float2(acc[mt][nt][half_ * 2 + 0],
                                       acc[mt][nt][half_ * 2 + 1]);
                if (c < 188) {
                    *(__half2*)(Xh + (long long)row * 188 + c) = __float22half2_rn(v);
                } else {
                    #pragma unroll
                    for (int q = 0; q < 2; q++) {
                        int cc = c + q;
                        if (cc >= 192 && cc < 239)
                            Oskip[(long long)row * 47 + (cc - 192)] = (q ? v.y : v.x);
                    }
                }
            }
        }
    }
}

// ---------------- layer-2 attention scores (fp16 xh) ----------------
__global__ void att_scores(const __half* __restrict__ xh,
                           const float* __restrict__ ws,
                           const float* __restrict__ wd,
                           float* __restrict__ asrc, float* __restrict__ adst,
                           int C, int stride)
{
    int i = blockIdx.x * blockDim.x + threadIdx.x;
    if (i >= NN * 4) return;
    int node = i >> 2, h = i & 3;
    const __half* row = xh + (long long)node * stride + h * C;
    const float* s_w = ws + h * C;
    const float* d_w = wd + h * C;
    float s1 = 0.f, s2 = 0.f;
    for (int c = 0; c < C; c++) {
        float v = __half2float(row[c]);
        s1 += v * s_w[c];
        s2 += v * d_w[c];
    }
    asrc[i] = s1;
    adst[i] = s2;
}

// ================= fused GAT aggregation (F=128), single-pass =============
__global__ __launch_bounds__(256) void gat_agg_128(
    const int* __restrict__ rowptr, const int* __restrict__ csr,
    const float* __restrict__ asrc, const float* __restrict__ adst,
    const __half* __restrict__ xh, const float* __restrict__ skipb,
    const float* __restrict__ bias, const float* __restrict__ skip_b,
    __nv_bfloat16* __restrict__ ahi, __nv_bfloat16* __restrict__ alo)
{
    int w = (blockIdx.x * blockDim.x + threadIdx.x) >> 5;
    if (w >= NN) return;
    int lane = threadIdx.x & 31;
    int beg = rowptr[w], end = rowptr[w + 1];
    float4 ad = *(const float4*)(adst + 4 * w);

    int h = lane >> 3;
    float4 s4 = make_float4(0.f, 0.f, 0.f, 0.f);
    float4 acc = make_float4(0.f, 0.f, 0.f, 0.f);
    #pragma unroll 2
    for (int e = beg; e < end; e++) {
        int s = csr[e];
        float4 a = *(const float4*)(asrc + 4 * s);
        float wx = __expf(lrelu(a.x + ad.x));
        float wy = __expf(lrelu(a.y + ad.y));
        float wz = __expf(lrelu(a.z + ad.z));
        float ww = __expf(lrelu(a.w + ad.w));
        s4.x += wx; s4.y += wy; s4.z += wz; s4.w += ww;
        float wl = (h == 0) ? wx : (h == 1) ? wy : (h == 2) ? wz : ww;
        uint2 raw = *(const uint2*)(xh + (long long)s * 128 + lane * 4);
        float2 p0 = __half22float2(*(const __half2*)&raw.x);
        float2 p1 = __half22float2(*(const __half2*)&raw.y);
        acc.x += wl * p0.x; acc.y += wl * p0.y;
        acc.z += wl * p1.x; acc.w += wl * p1.y;
    }
    float wsh = (h == 0) ? s4.x : (h == 1) ? s4.y : (h == 2) ? s4.z : s4.w;
    float inv = 1.f / (wsh + 1e-16f);

    int base = w * 128 + lane * 4;
    float4 sk = *(const float4*)(skipb + base);
    float4 bi = *(const float4*)(bias + lane * 4);
    float4 sb = *(const float4*)(skip_b + lane * 4);
    float4 o;
    o.x = acc.x * inv + sk.x + bi.x + sb.x;
    o.y = acc.y * inv + sk.y + bi.y + sb.y;
    o.z = acc.z * inv + sk.z + bi.z + sb.z;
    o.w = acc.w * inv + sk.w + bi.w + sb.w;
    o.x = o.x > 0.f ? o.x : expm1f(o.x);
    o.y = o.y > 0.f ? o.y : expm1f(o.y);
    o.z = o.z > 0.f ? o.z : expm1f(o.z);
    o.w = o.w > 0.f ? o.w : expm1f(o.w);

    __nv_bfloat16 h0, l0, h1, l1, h2, l2, h3, l3;
    split_bf16(o.x, h0, l0); split_bf16(o.y, h1, l1);
    split_bf16(o.z, h2, l2); split_bf16(o.w, h3, l3);
    uint2 ph, pl;
    ph.x = pack_bf16(h0, h1); ph.y = pack_bf16(h2, h3);
    pl.x = pack_bf16(l0, l1); pl.y = pack_bf16(l2, l3);
    *(uint2*)((char*)ahi + (long long)base * 2) = ph;
    *(uint2*)((char*)alo + (long long)base * 2) = pl;
}

// ================= fused GAT aggregation (layer 2, head-mean) =============
__global__ __launch_bounds__(256) void gat_agg_188(
    const int* __restrict__ rowptr, const int* __restrict__ csr,
    const float* __restrict__ asrc, const float* __restrict__ adst,
    const __half* __restrict__ xh, const float* __restrict__ skipb,
    const float* __restrict__ bias2, const float* __restrict__ skip_b2,
    float* __restrict__ out)
{
    int w = (blockIdx.x * blockDim.x + threadIdx.x) >> 5;
    if (w >= NN) return;
    int lane = threadIdx.x & 31;
    int beg = rowptr[w], end = rowptr[w + 1];
    float4 ad = *(const float4*)(adst + 4 * w);

    float4 s4 = make_float4(0.f, 0.f, 0.f, 0.f);
    float a00 = 0.f, a01 = 0.f, a02 = 0.f, a03 = 0.f;
    float a10 = 0.f, a11 = 0.f, a12 = 0.f, a13 = 0.f;
    int o1 = lane + 32;
    #pragma unroll 2
    for (int e = beg; e < end; e++) {
        int s = csr[e];
        float4 a = *(const float4*)(asrc + 4 * s);
        float wx = __expf(lrelu(a.x + ad.x));
        float wy = __expf(lrelu(a.y + ad.y));
        float wz = __expf(lrelu(a.z + ad.z));
        float ww = __expf(lrelu(a.w + ad.w));
        s4.x += wx; s4.y += wy; s4.z += wz; s4.w += ww;
        const __half* row = xh + (long long)s * 188;
        a00 += wx * __half2float(row[lane]);
        a01 += wy * __half2float(row[47 + lane]);
        a02 += wz * __half2float(row[94 + lane]);
        a03 += ww * __half2float(row[141 + lane]);
        if (o1 < 47) {
            a10 += wx * __half2float(row[o1]);
            a11 += wy * __half2float(row[47 + o1]);
            a12 += wz * __half2float(row[94 + o1]);
            a13 += ww * __half2float(row[141 + o1]);
        }
    }
    float ix = 1.f / (s4.x + 1e-16f);
    float iy = 1.f / (s4.y + 1e-16f);
    float iz = 1.f / (s4.z + 1e-16f);
    float iw = 1.f / (s4.w + 1e-16f);

    {
        int o = lane;
        float v = 0.25f * (a00 * ix + a01 * iy + a02 * iz + a03 * iw);
        out[w * 47 + o] = v + bias2[o] + skipb[w * 47 + o] + skip_b2[o];
    }
    if (o1 < 47) {
        float v = 0.25f * (a10 * ix + a11 * iy + a12 * iz + a13 * iw);
        out[w * 47 + o1] = v + bias2[o1] + skipb[w * 47 + o1] + skip_b2[o1];
    }
}

// ---------------- launch ----------------
extern "C" void kernel_launch(void* const* d_in, const int* in_sizes, int n_in,
                              void* d_out, int out_size)
{
    const float* x        = (const float*)d_in[0];
    const int*   ei       = (const int*)  d_in[1];
    const float* lin_w0   = (const float*)d_in[2];
    const float* att_src0 = (const float*)d_in[3];
    const float* att_dst0 = (const float*)d_in[4];
    const float* bias0    = (const float*)d_in[5];
    const float* skip_w0  = (const float*)d_in[6];
    const float* skip_b0  = (const float*)d_in[7];
    const float* lin_w1   = (const float*)d_in[8];
    const float* att_src1 = (const float*)d_in[9];
    const float* att_dst1 = (const float*)d_in[10];
    const float* bias1    = (const float*)d_in[11];
    const float* skip_w1  = (const float*)d_in[12];
    const float* skip_b1  = (const float*)d_in[13];
    const float* lin_w2   = (const float*)d_in[14];
    const float* att_src2 = (const float*)d_in[15];
    const float* att_dst2 = (const float*)d_in[16];
    const float* bias2    = (const float*)d_in[17];
    const float* skip_w2  = (const float*)d_in[18];
    const float* skip_b2  = (const float*)d_in[19];
    float* out = (float*)d_out;

    __half* xh_h; float *skipb, *asrc, *adst;
    __nv_bfloat16 *ahi, *alo, *wbhi, *wblo;
    int *deg, *ex, *bsum, *rowptr, *cursor, *csr;
    cudaGetSymbolAddress((void**)&xh_h,   g_xh_h);
    cudaGetSymbolAddress((void**)&skipb,  g_skip);
    cudaGetSymbolAddress((void**)&ahi,    g_ahi);
    cudaGetSymbolAddress((void**)&alo,    g_alo);
    cudaGetSymbolAddress((void**)&wbhi,   g_wbhi);
    cudaGetSymbolAddress((void**)&wblo,   g_wblo);
    cudaGetSymbolAddress((void**)&asrc,   g_asrc);
    cudaGetSymbolAddress((void**)&adst,   g_adst);
    cudaGetSymbolAddress((void**)&deg,    g_deg);
    cudaGetSymbolAddress((void**)&ex,     g_ex);
    cudaGetSymbolAddress((void**)&bsum,   g_bsum);
    cudaGetSymbolAddress((void**)&rowptr, g_rowptr);
    cudaGetSymbolAddress((void**)&cursor, g_cursor);
    cudaGetSymbolAddress((void**)&csr,    g_csr);

    static int smem_set = 0;
    if (!smem_set) {
        cudaFuncSetAttribute(gemm_dual_128, cudaFuncAttributeMaxDynamicSharedMemorySize, SM_TOTAL);
        cudaFuncSetAttribute(gemm_l2,       cudaFuncAttributeMaxDynamicSharedMemorySize, SM_TOTAL);
        smem_set = 1;
    }

    const int GB   = (NN + 127) / 128;               // 391 GEMM row blocks
    const int EBLK = (ETOT + 255) / 256;             // 3321
    const int WGRD = (NN * 32 + 255) / 256;          // 6250 (warp per node)

    // ---------- conversions (weights + x, one kernel) ----------
    conv_all<<<384 + (NN * 32 + 255) / 256, 256>>>(
        lin_w0, skip_w0, lin_w1, skip_w1, lin_w2, skip_w2, x,
        wbhi, wblo, ahi, alo);

    // ---------- CSR build (once, shared by all 3 layers) ----------
    cudaMemsetAsync(deg, 0, NN * sizeof(int));
    k_count<<<EBLK, 256>>>(ei, deg);
    k_scan1<<<NB_SCAN, 256>>>(deg, ex, bsum);
    k_scan23<<<NB_SCAN, 256>>>(ex, bsum, rowptr, cursor);
    k_fill<<<EBLK, 256>>>(ei, cursor, csr);

    // ---------- layer 0 ----------
    gemm_dual_128<<<GB, 512, SM_TOTAL>>>(ahi, alo, wbhi, wblo,
                                         att_src0, att_dst0, xh_h, skipb, asrc, adst);
    gat_agg_128<<<WGRD, 256>>>(rowptr, csr, asrc, adst, xh_h, skipb, bias0, skip_b0, ahi, alo);

    // ---------- layer 1 ----------
    gemm_dual_128<<<GB, 512, SM_TOTAL>>>(ahi, alo, wbhi + 256 * 136, wblo + 256 * 136,
                                         att_src1, att_dst1, xh_h, skipb, asrc, adst);
    gat_agg_128<<<WGRD, 256>>>(rowptr, csr, asrc, adst, xh_h, skipb, bias1, skip_b1, ahi, alo);

    // ---------- layer 2 ----------
    gemm_l2<<<GB, 512, SM_TOTAL>>>(ahi, alo, wbhi + 512 * 136, wblo + 512 * 136, xh_h, skipb);
    att_scores<<<(NN * 4 + 255) / 256, 256>>>(xh_h, att_src2, att_dst2, asrc, adst, 47, 188);
    gat_agg_188<<<WGRD, 256>>>(rowptr, csr, asrc, adst, xh_h, skipb, bias2, skip_b2, out);
}

// round 12
// speedup vs baseline: 3.0021x; 1.2181x over previous
#include <cuda_runtime.h>
#include <cuda_bf16.h>
#include <cuda_fp16.h>
#include <math.h>
#include <stdint.h>

#define NN 50000
#define EE 800000
#define ETOT (EE + NN)
#define NB_SCAN 196   // ceil(50000/256)

// ---------------- scratch (no allocations allowed) ----------------
__device__ __align__(16) __half         g_xh_h[NN * 188];   // lin output, fp16
__device__ __align__(16) float          g_skip[NN * 128];   // skip GEMM output (fp32)
__device__ __align__(16) __nv_bfloat16  g_ahi [NN * 128];   // A image hi
__device__ __align__(16) __nv_bfloat16  g_alo [NN * 128];   // A image lo
__device__ __align__(16) __nv_bfloat16  g_wbhi[768 * 136];  // weight images (3 layers)
__device__ __align__(16) __nv_bfloat16  g_wblo[768 * 136];
__device__ float    g_asrc[NN * 4];
__device__ float    g_adst[NN * 4];
// CSR scratch
__device__ int      g_deg   [NN];
__device__ int      g_ex    [NN];
__device__ int      g_bsum  [256];
__device__ int      g_rowptr[NN + 1];
__device__ int      g_cursor[NN];
__device__ int      g_csr   [ETOT];

// ---------------- helpers ----------------
__device__ __forceinline__ float lrelu(float e) { return fmaxf(e, 0.2f * e); }

__device__ __forceinline__ uint32_t smem_u32(const void* p) {
    uint32_t a;
    asm("{ .reg .u64 t; cvta.to.shared.u64 t, %1; cvt.u32.u64 %0, t; }"
        : "=r"(a) : "l"(p));
    return a;
}

__device__ __forceinline__ void split_bf16(float v, __nv_bfloat16& h, __nv_bfloat16& l) {
    h = __float2bfloat16_rn(v);
    l = __float2bfloat16_rn(v - __bfloat162float(h));
}

__device__ __forceinline__ uint32_t pack_bf16(__nv_bfloat16 a, __nv_bfloat16 b) {
    return (uint32_t)__bfloat16_as_ushort(a) |
           ((uint32_t)__bfloat16_as_ushort(b) << 16);
}

__device__ __forceinline__ void ldsm_x4(uint32_t& r0, uint32_t& r1,
                                        uint32_t& r2, uint32_t& r3, uint32_t addr) {
    asm volatile("ldmatrix.sync.aligned.m8n8.x4.shared.b16 {%0,%1,%2,%3}, [%4];"
                 : "=r"(r0), "=r"(r1), "=r"(r2), "=r"(r3) : "r"(addr));
}

__device__ __forceinline__ void mma_bf16(float* c, const uint32_t* a, const uint32_t* b) {
    asm volatile(
        "mma.sync.aligned.m16n8k16.row.col.f32.bf16.bf16.f32 "
        "{%0,%1,%2,%3}, {%4,%5,%6,%7}, {%8,%9}, {%0,%1,%2,%3};"
        : "+f"(c[0]), "+f"(c[1]), "+f"(c[2]), "+f"(c[3])
        : "r"(a[0]), "r"(a[1]), "r"(a[2]), "r"(a[3]), "r"(b[0]), "r"(b[1]));
}

// SMEM layout (bytes), stride 136 bf16 = 272B per row
#define AST       136
#define BST       136
#define SM_AHI    0
#define SM_ALO    (128 * AST * 2)                 // 34816
#define SM_BHI    (SM_ALO + 128 * AST * 2)        // 69632
#define SM_BLO    (SM_BHI + 256 * BST * 2)        // 139264
#define SM_TOTAL  (SM_BLO + 256 * BST * 2)        // 208896

// ================= merged conversion kernel (also zeroes deg) =============
__global__ void conv_all(
    const float* __restrict__ w0l, const float* __restrict__ w0s,
    const float* __restrict__ w1l, const float* __restrict__ w1s,
    const float* __restrict__ w2l, const float* __restrict__ w2s,
    const float* __restrict__ X,
    __nv_bfloat16* __restrict__ whi, __nv_bfloat16* __restrict__ wlo,
    __nv_bfloat16* __restrict__ ahi, __nv_bfloat16* __restrict__ alo,
    int* __restrict__ deg)
{
    int bx = blockIdx.x;
    if (bx < 384) {
        int di = bx * 256 + threadIdx.x;
        if (di < NN) deg[di] = 0;
        int idx = bx * 256 + threadIdx.x;          // over 768*128
        int n = idx >> 7, k = idx & 127;
        int layer = n >> 8, nl = n & 255;
        float v = 0.f;
        if (layer == 0) {
            v = (nl < 128) ? w0l[k * 128 + nl] : w0s[k * 128 + (nl - 128)];
        } else if (layer == 1) {
            v = (nl < 128) ? w1l[k * 128 + nl] : w1s[k * 128 + (nl - 128)];
        } else {
            if (nl < 188) v = w2l[k * 188 + nl];
            else if (nl >= 192 && nl < 239) v = w2s[k * 47 + (nl - 192)];
        }
        __nv_bfloat16 h, l;
        split_bf16(v, h, l);
        whi[n * 136 + k] = h;
        wlo[n * 136 + k] = l;
    } else {
        int idx = (bx - 384) * 256 + threadIdx.x;  // over NN*32 float4s
        if (idx >= NN * 32) return;
        float4 v = *(const float4*)(X + (long long)idx * 4);
        __nv_bfloat16 h0, l0, h1, l1, h2, l2, h3, l3;
        split_bf16(v.x, h0, l0); split_bf16(v.y, h1, l1);
        split_bf16(v.z, h2, l2); split_bf16(v.w, h3, l3);
        uint2 ph, pl;
        ph.x = pack_bf16(h0, h1); ph.y = pack_bf16(h2, h3);
        pl.x = pack_bf16(l0, l1); pl.y = pack_bf16(l2, l3);
        *(uint2*)((char*)ahi + (long long)idx * 8) = ph;
        *(uint2*)((char*)alo + (long long)idx * 8) = pl;
    }
}

// ================= CSR build =================
__global__ void k_count(const int* __restrict__ ei, int* __restrict__ deg) {
    int i = blockIdx.x * blockDim.x + threadIdx.x;
    if (i >= ETOT) return;
    int d = (i < EE) ? ei[EE + i] : i - EE;
    atomicAdd(&deg[d], 1);
}
__global__ void k_scan1(const int* __restrict__ deg, int* __restrict__ ex,
                        int* __restrict__ bsum) {
    __shared__ int sh[256];
    int t = threadIdx.x;
    int i = blockIdx.x * 256 + t;
    int v = (i < NN) ? deg[i] : 0;
    sh[t] = v;
    __syncthreads();
    for (int off = 1; off < 256; off <<= 1) {
        int a = (t >= off) ? sh[t - off] : 0;
        __syncthreads();
        sh[t] += a;
        __syncthreads();
    }
    if (i < NN) ex[i] = sh[t] - v;
    if (t == 255) bsum[blockIdx.x] = sh[255];
}
__global__ void k_scan23(const int* __restrict__ ex, const int* __restrict__ bsum,
                         int* __restrict__ rowptr, int* __restrict__ cursor) {
    __shared__ int sh[256];
    int t = threadIdx.x, b = blockIdx.x;
    sh[t] = (t < b) ? bsum[t] : 0;     // b <= 195 < 256
    __syncthreads();
    for (int off = 128; off; off >>= 1) {
        if (t < off) sh[t] += sh[t + off];
        __syncthreads();
    }
    int bpre = sh[0];
    int i = b * 256 + t;
    if (i < NN) {
        int r = ex[i] + bpre;
        rowptr[i] = r;
        cursor[i] = r;
    }
    if (i == 0) rowptr[NN] = ETOT;
}
__global__ void k_fill(const int* __restrict__ ei, int* __restrict__ cursor,
                       int* __restrict__ csr) {
    int i = blockIdx.x * blockDim.x + threadIdx.x;
    if (i >= ETOT) return;
    int s, d;
    if (i < EE) { s = ei[i]; d = ei[EE + i]; } else { s = d = i - EE; }
    int pos = atomicAdd(&cursor[d], 1);
    csr[pos] = s;
}

// ============ staging (pure copies) + mma mainloop ============
__device__ __forceinline__ void stage_A2(char* sm, const __nv_bfloat16* __restrict__ ahi,
                                         const __nv_bfloat16* __restrict__ alo,
                                         int row0, int tid) {
    #pragma unroll
    for (int jj = 0; jj < 4; jj++) {
        int i = tid + jj * 512;          // 0..2047
        int r = i >> 4, q = i & 15;      // row, uint4 idx (16B)
        uint4 vh = make_uint4(0, 0, 0, 0), vl = make_uint4(0, 0, 0, 0);
        if (row0 + r < NN) {
            long long bofs = ((long long)(row0 + r) * 128 + q * 8) * 2;
            vh = *(const uint4*)((const char*)ahi + bofs);
            vl = *(const uint4*)((const char*)alo + bofs);
        }
        *(uint4*)(sm + SM_AHI + r * (AST * 2) + q * 16) = vh;
        *(uint4*)(sm + SM_ALO + r * (AST * 2) + q * 16) = vl;
    }
}

__device__ __forceinline__ void stage_B2(char* sm, const __nv_bfloat16* __restrict__ whi,
                                         const __nv_bfloat16* __restrict__ wlo, int tid) {
    #pragma unroll
    for (int jj = 0; jj < 9; jj++) {
        int i = tid + jj * 512;
        if (i < 4352) {
            *(uint4*)(sm + SM_BHI + i * 16) = *(const uint4*)((const char*)whi + i * 16);
            *(uint4*)(sm + SM_BLO + i * 16) = *(const uint4*)((const char*)wlo + i * 16);
        }
    }
}

__device__ __forceinline__ void mma_mainloop(char* sm, float acc[2][8][4],
                                             int wid, int lane) {
    const uint32_t sb = smem_u32(sm);
    const int wm = wid >> 2, wn = wid & 3;
    const int m0r = wm * 32, n0 = wn * 64;
    const int ar = (lane & 15), ak = (lane >> 4) * 8;
    const int bn = ((lane >> 4) * 8) + (lane & 7);
    const int bk = ((lane >> 3) & 1) * 8;

    #pragma unroll
    for (int ks = 0; ks < 8; ks++) {
        int k0 = ks * 16;
        uint32_t ahi[2][4], alo[2][4], bhi[8][2], blo[8][2];
        #pragma unroll
        for (int mt = 0; mt < 2; mt++) {
            uint32_t addr = sb + SM_AHI + (m0r + mt * 16 + ar) * (AST * 2) + (k0 + ak) * 2;
            ldsm_x4(ahi[mt][0], ahi[mt][1], ahi[mt][2], ahi[mt][3], addr);
        }
        #pragma unroll
        for (int p = 0; p < 4; p++) {
            uint32_t addr = sb + SM_BHI + (n0 + p * 16 + bn) * (BST * 2) + (k0 + bk) * 2;
            ldsm_x4(bhi[2 * p][0], bhi[2 * p][1], bhi[2 * p + 1][0], bhi[2 * p + 1][1], addr);
        }
        #pragma unroll
        for (int mt = 0; mt < 2; mt++)
            #pragma unroll
            for (int nt = 0; nt < 8; nt++)
                mma_bf16(acc[mt][nt], ahi[mt], bhi[nt]);
        #pragma unroll
        for (int p = 0; p < 4; p++) {
            uint32_t addr = sb + SM_BLO + (n0 + p * 16 + bn) * (BST * 2) + (k0 + bk) * 2;
            ldsm_x4(blo[2 * p][0], blo[2 * p][1], blo[2 * p + 1][0], blo[2 * p + 1][1], addr);
        }
        #pragma unroll
        for (int mt = 0; mt < 2; mt++)
            #pragma unroll
            for (int nt = 0; nt < 8; nt++)
                mma_bf16(acc[mt][nt], ahi[mt], blo[nt]);
        #pragma unroll
        for (int mt = 0; mt < 2; mt++) {
            uint32_t addr = sb + SM_ALO + (m0r + mt * 16 + ar) * (AST * 2) + (k0 + ak) * 2;
            ldsm_x4(alo[mt][0], alo[mt][1], alo[mt][2], alo[mt][3], addr);
        }
        #pragma unroll
        for (int mt = 0; mt < 2; mt++)
            #pragma unroll
            for (int nt = 0; nt < 8; nt++)
                mma_bf16(acc[mt][nt], alo[mt], bhi[nt]);
    }
}

// ================= dual GEMM, layers 0/1 + fused attention scores =========
__global__ __launch_bounds__(512, 1) void gemm_dual_128(
    const __nv_bfloat16* __restrict__ ahi, const __nv_bfloat16* __restrict__ alo,
    const __nv_bfloat16* __restrict__ whi, const __nv_bfloat16* __restrict__ wlo,
    const float* __restrict__ AttS, const float* __restrict__ AttD,
    __half* __restrict__ Xh, float* __restrict__ Oskip,
    float* __restrict__ asrc, float* __restrict__ adst)
{
    extern __shared__ char sm[];
    const int tid = threadIdx.x;
    const int wid = tid >> 5, lane = tid & 31;
    const int row0 = blockIdx.x << 7;

    stage_A2(sm, ahi, alo, row0, tid);
    stage_B2(sm, whi, wlo, tid);
    __syncthreads();

    float acc[2][8][4];
    #pragma unroll
    for (int i = 0; i < 2; i++)
        #pragma unroll
        for (int j = 0; j < 8; j++)
            #pragma unroll
            for (int q = 0; q < 4; q++) acc[i][j][q] = 0.f;

    mma_mainloop(sm, acc, wid, lane);

    const int wm = wid >> 2, wn = wid & 3;
    const int g = lane >> 2, t = lane & 3;

    #pragma unroll
    for (int mt = 0; mt < 2; mt++) {
        #pragma unroll
        for (int half_ = 0; half_ < 2; half_++) {
            int row = row0 + wm * 32 + mt * 16 + g + half_ * 8;
            if (row >= NN) continue;
            #pragma unroll
            for (int nt = 0; nt < 8; nt++) {
                int c = wn * 64 + nt * 8 + t * 2;
                float2 v = make_float2(acc[mt][nt][half_ * 2 + 0],
                                       acc[mt][nt][half_ * 2 + 1]);
                if (c < 128)
                    *(__half2*)(Xh + (long long)row * 128 + c) = __float22half2_rn(v);
                else
                    *(float2*)(Oskip + (long long)row * 128 + (c - 128)) = v;
            }
        }
    }

    if (wn < 2) {
        #pragma unroll
        for (int mt = 0; mt < 2; mt++) {
            #pragma unroll
            for (int half_ = 0; half_ < 2; half_++) {
                float ps0 = 0.f, ps1 = 0.f, pd0 = 0.f, pd1 = 0.f;
                #pragma unroll
                for (int nt = 0; nt < 8; nt++) {
                    #pragma unroll
                    for (int q = 0; q < 2; q++) {
                        int c = wn * 64 + nt * 8 + t * 2 + q;
                        float v = acc[mt][nt][half_ * 2 + q];
                        float cs = AttS[c], cd = AttD[c];
                        if (nt < 4) { ps0 += v * cs; pd0 += v * cd; }
                        else        { ps1 += v * cs; pd1 += v * cd; }
                    }
                }
                ps0 += __shfl_xor_sync(0xFFFFFFFFu, ps0, 1);
                ps0 += __shfl_xor_sync(0xFFFFFFFFu, ps0, 2);
                ps1 += __shfl_xor_sync(0xFFFFFFFFu, ps1, 1);
                ps1 += __shfl_xor_sync(0xFFFFFFFFu, ps1, 2);
                pd0 += __shfl_xor_sync(0xFFFFFFFFu, pd0, 1);
                pd0 += __shfl_xor_sync(0xFFFFFFFFu, pd0, 2);
                pd1 += __shfl_xor_sync(0xFFFFFFFFu, pd1, 1);
                pd1 += __shfl_xor_sync(0xFFFFFFFFu, pd1, 2);
                int row = row0 + wm * 32 + mt * 16 + g + half_ * 8;
                if (t == 0 && row < NN) {
                    int h0 = wn * 2, h1 = wn * 2 + 1;
                    asrc[row * 4 + h0] = ps0;
                    asrc[row * 4 + h1] = ps1;
                    adst[row * 4 + h0] = pd0;
                    adst[row * 4 + h1] = pd1;
                }
            }
        }
    }
}

// ================= layer-2 GEMM + fused attention scores ==================
__global__ __launch_bounds__(512, 1) void gemm_l2(
    const __nv_bfloat16* __restrict__ ahi, const __nv_bfloat16* __restrict__ alo,
    const __nv_bfloat16* __restrict__ whi, const __nv_bfloat16* __restrict__ wlo,
    const float* __restrict__ AttS, const float* __restrict__ AttD,
    __half* __restrict__ Xh, float* __restrict__ Oskip,
    float* __restrict__ asrc, float* __restrict__ adst)
{
    extern __shared__ char sm[];
    const int tid = threadIdx.x;
    const int wid = tid >> 5, lane = tid & 31;
    const int row0 = blockIdx.x << 7;

    stage_A2(sm, ahi, alo, row0, tid);
    stage_B2(sm, whi, wlo, tid);
    __syncthreads();

    float acc[2][8][4];
    #pragma unroll
    for (int i = 0; i < 2; i++)
        #pragma unroll
        for (int j = 0; j < 8; j++)
            #pragma unroll
            for (int q = 0; q < 4; q++) acc[i][j][q] = 0.f;

    mma_mainloop(sm, acc, wid, lane);

    const int wm = wid >> 2, wn = wid & 3;
    const int g = lane >> 2, t = lane & 3;
    #pragma unroll
    for (int mt = 0; mt < 2; mt++) {
        #pragma unroll
        for (int half_ = 0; half_ < 2; half_++) {
            int row = row0 + wm * 32 + mt * 16 + g + half_ * 8;
            if (row >= NN) continue;
            #pragma unroll
            for (int nt = 0; nt < 8; nt++) {
                int c = wn * 64 + nt * 8 + t * 2;
                float2 v = make_float2(acc[mt][nt][half_ * 2 + 0],
                                       acc[mt][nt][half_ * 2 + 1]);
                if (c < 188) {
                    *(__half2*)(Xh + (long long)row * 188 + c) = __float22half2_rn(v);
                } else {
                    #pragma unroll
                    for (int q = 0; q < 2; q++) {
                        int cc = c + q;
                        if (cc >= 192 && cc < 239)
                            Oskip[(long long)row * 47 + (cc - 192)] = (q ? v.y : v.x);
                    }
                }
            }
        }
    }

    // ---- fused layer-2 attention scores (head = c/47) ----
    __syncthreads();                   // all warps done with A/B smem
    float* satt = (float*)sm;          // reuse: 128 rows x [4 heads x {s,d}] = 1024 f
    for (int i = tid; i < 128 * 8; i += 512) satt[i] = 0.f;
    __syncthreads();

    #pragma unroll
    for (int mt = 0; mt < 2; mt++) {
        #pragma unroll
        for (int half_ = 0; half_ < 2; half_++) {
            float ps[4] = {0.f, 0.f, 0.f, 0.f}, pd[4] = {0.f, 0.f, 0.f, 0.f};
            #pragma unroll
            for (int nt = 0; nt < 8; nt++) {
                #pragma unroll
                for (int q = 0; q < 2; q++) {
                    int c = wn * 64 + nt * 8 + t * 2 + q;
                    if (c < 188) {
                        float v = acc[mt][nt][half_ * 2 + q];
                        int h = c / 47;
                        ps[h] += v * AttS[c];
                        pd[h] += v * AttD[c];
                    }
                }
            }
            #pragma unroll
            for (int h = 0; h < 4; h++) {
                ps[h] += __shfl_xor_sync(0xFFFFFFFFu, ps[h], 1);
                ps[h] += __shfl_xor_sync(0xFFFFFFFFu, ps[h], 2);
                pd[h] += __shfl_xor_sync(0xFFFFFFFFu, pd[h], 1);
                pd[h] += __shfl_xor_sync(0xFFFFFFFFu, pd[h], 2);
            }
            if (t == 0) {
                int rloc = wm * 32 + mt * 16 + g + half_ * 8;
                #pragma unroll
                for (int h = 0; h < 4; h++) {
                    atomicAdd(&satt[rloc * 8 + h * 2 + 0], ps[h]);
                    atomicAdd(&satt[rloc * 8 + h * 2 + 1], pd[h]);
                }
            }
        }
    }
    __syncthreads();
    for (int i = tid; i < 128 * 4; i += 512) {
        int rloc = i >> 2, h = i & 3;
        int row = row0 + rloc;
        if (row < NN) {
            asrc[row * 4 + h] = satt[rloc * 8 + h * 2 + 0];
            adst[row * 4 + h] = satt[rloc * 8 + h * 2 + 1];
        }
    }
}

// ================= fused GAT aggregation (F=128), single-pass =============
// per-lane single-head exp: lane's head h = lane>>3
__global__ __launch_bounds__(256) void gat_agg_128(
    const int* __restrict__ rowptr, const int* __restrict__ csr,
    const float* __restrict__ asrc, const float* __restrict__ adst,
    const __half* __restrict__ xh, const float* __restrict__ skipb,
    const float* __restrict__ bias, const float* __restrict__ skip_b,
    __nv_bfloat16* __restrict__ ahi, __nv_bfloat16* __restrict__ alo)
{
    int w = (blockIdx.x * blockDim.x + threadIdx.x) >> 5;
    if (w >= NN) return;
    int lane = threadIdx.x & 31;
    int h = lane >> 3;
    int beg = rowptr[w], end = rowptr[w + 1];
    float adh = adst[4 * w + h];

    float sh = 0.f;
    float4 acc = make_float4(0.f, 0.f, 0.f, 0.f);
    #pragma unroll 4
    for (int e = beg; e < end; e++) {
        int s = csr[e];
        float as = asrc[4 * s + h];
        float wl = __expf(lrelu(as + adh));
        sh += wl;
        uint2 raw = *(const uint2*)(xh + (long long)s * 128 + lane * 4);
        float2 p0 = __half22float2(*(const __half2*)&raw.x);
        float2 p1 = __half22float2(*(const __half2*)&raw.y);
        acc.x += wl * p0.x; acc.y += wl * p0.y;
        acc.z += wl * p1.x; acc.w += wl * p1.y;
    }
    float inv = 1.f / (sh + 1e-16f);

    int base = w * 128 + lane * 4;
    float4 sk = *(const float4*)(skipb + base);
    float4 bi = *(const float4*)(bias + lane * 4);
    float4 sb = *(const float4*)(skip_b + lane * 4);
    float4 o;
    o.x = acc.x * inv + sk.x + bi.x + sb.x;
    o.y = acc.y * inv + sk.y + bi.y + sb.y;
    o.z = acc.z * inv + sk.z + bi.z + sb.z;
    o.w = acc.w * inv + sk.w + bi.w + sb.w;
    o.x = o.x > 0.f ? o.x : expm1f(o.x);
    o.y = o.y > 0.f ? o.y : expm1f(o.y);
    o.z = o.z > 0.f ? o.z : expm1f(o.z);
    o.w = o.w > 0.f ? o.w : expm1f(o.w);

    __nv_bfloat16 h0, l0, h1, l1, h2, l2, h3, l3;
    split_bf16(o.x, h0, l0); split_bf16(o.y, h1, l1);
    split_bf16(o.z, h2, l2); split_bf16(o.w, h3, l3);
    uint2 ph, pl;
    ph.x = pack_bf16(h0, h1); ph.y = pack_bf16(h2, h3);
    pl.x = pack_bf16(l0, l1); pl.y = pack_bf16(l2, l3);
    *(uint2*)((char*)ahi + (long long)base * 2) = ph;
    *(uint2*)((char*)alo + (long long)base * 2) = pl;
}

// ================= fused GAT aggregation (layer 2, head-mean) =============
__global__ __launch_bounds__(256) void gat_agg_188(
    const int* __restrict__ rowptr, const int* __restrict__ csr,
    const float* __restrict__ asrc, const float* __restrict__ adst,
    const __half* __restrict__ xh, const float* __restrict__ skipb,
    const float* __restrict__ bias2, const float* __restrict__ skip_b2,
    float* __restrict__ out)
{
    int w = (blockIdx.x * blockDim.x + threadIdx.x) >> 5;
    if (w >= NN) return;
    int lane = threadIdx.x & 31;
    int beg = rowptr[w], end = rowptr[w + 1];
    float4 ad = *(const float4*)(adst + 4 * w);

    float4 s4 = make_float4(0.f, 0.f, 0.f, 0.f);
    float a00 = 0.f, a01 = 0.f, a02 = 0.f, a03 = 0.f;
    float a10 = 0.f, a11 = 0.f, a12 = 0.f, a13 = 0.f;
    int o1 = lane + 32;
    #pragma unroll 2
    for (int e = beg; e < end; e++) {
        int s = csr[e];
        float4 a = *(const float4*)(asrc + 4 * s);
        float wx = __expf(lrelu(a.x + ad.x));
        float wy = __expf(lrelu(a.y + ad.y));
        float wz = __expf(lrelu(a.z + ad.z));
        float ww = __expf(lrelu(a.w + ad.w));
        s4.x += wx; s4.y += wy; s4.z += wz; s4.w += ww;
        const __half* row = xh + (long long)s * 188;
        a00 += wx * __half2float(row[lane]);
        a01 += wy * __half2float(row[47 + lane]);
        a02 += wz * __half2float(row[94 + lane]);
        a03 += ww * __half2float(row[141 + lane]);
        if (o1 < 47) {
            a10 += wx * __half2float(row[o1]);
            a11 += wy * __half2float(row[47 + o1]);
            a12 += wz * __half2float(row[94 + o1]);
            a13 += ww * __half2float(row[141 + o1]);
        }
    }
    float ix = 1.f / (s4.x + 1e-16f);
    float iy = 1.f / (s4.y + 1e-16f);
    float iz = 1.f / (s4.z + 1e-16f);
    float iw = 1.f / (s4.w + 1e-16f);

    {
        int o = lane;
        float v = 0.25f * (a00 * ix + a01 * iy + a02 * iz + a03 * iw);
        out[w * 47 + o] = v + bias2[o] + skipb[w * 47 + o] + skip_b2[o];
    }
    if (o1 < 47) {
        float v = 0.25f * (a10 * ix + a11 * iy + a12 * iz + a13 * iw);
        out[w * 47 + o1] = v + bias2[o1] + skipb[w * 47 + o1] + skip_b2[o1];
    }
}

// ---------------- launch ----------------
extern "C" void kernel_launch(void* const* d_in, const int* in_sizes, int n_in,
                              void* d_out, int out_size)
{
    const float* x        = (const float*)d_in[0];
    const int*   ei       = (const int*)  d_in[1];
    const float* lin_w0   = (const float*)d_in[2];
    const float* att_src0 = (const float*)d_in[3];
    const float* att_dst0 = (const float*)d_in[4];
    const float* bias0    = (const float*)d_in[5];
    const float* skip_w0  = (const float*)d_in[6];
    const float* skip_b0  = (const float*)d_in[7];
    const float* lin_w1   = (const float*)d_in[8];
    const float* att_src1 = (const float*)d_in[9];
    const float* att_dst1 = (const float*)d_in[10];
    const float* bias1    = (const float*)d_in[11];
    const float* skip_w1  = (const float*)d_in[12];
    const float* skip_b1  = (const float*)d_in[13];
    const float* lin_w2   = (const float*)d_in[14];
    const float* att_src2 = (const float*)d_in[15];
    const float* att_dst2 = (const float*)d_in[16];
    const float* bias2    = (const float*)d_in[17];
    const float* skip_w2  = (const float*)d_in[18];
    const float* skip_b2  = (const float*)d_in[19];
    float* out = (float*)d_out;

    __half* xh_h; float *skipb, *asrc, *adst;
    __nv_bfloat16 *ahi, *alo, *wbhi, *wblo;
    int *deg, *ex, *bsum, *rowptr, *cursor, *csr;
    cudaGetSymbolAddress((void**)&xh_h,   g_xh_h);
    cudaGetSymbolAddress((void**)&skipb,  g_skip);
    cudaGetSymbolAddress((void**)&ahi,    g_ahi);
    cudaGetSymbolAddress((void**)&alo,    g_alo);
    cudaGetSymbolAddress((void**)&wbhi,   g_wbhi);
    cudaGetSymbolAddress((void**)&wblo,   g_wblo);
    cudaGetSymbolAddress((void**)&asrc,   g_asrc);
    cudaGetSymbolAddress((void**)&adst,   g_adst);
    cudaGetSymbolAddress((void**)&deg,    g_deg);
    cudaGetSymbolAddress((void**)&ex,     g_ex);
    cudaGetSymbolAddress((void**)&bsum,   g_bsum);
    cudaGetSymbolAddress((void**)&rowptr, g_rowptr);
    cudaGetSymbolAddress((void**)&cursor, g_cursor);
    cudaGetSymbolAddress((void**)&csr,    g_csr);

    static int smem_set = 0;
    if (!smem_set) {
        cudaFuncSetAttribute(gemm_dual_128, cudaFuncAttributeMaxDynamicSharedMemorySize, SM_TOTAL);
        cudaFuncSetAttribute(gemm_l2,       cudaFuncAttributeMaxDynamicSharedMemorySize, SM_TOTAL);
        smem_set = 1;
    }

    const int GB   = (NN + 127) / 128;               // 391 GEMM row blocks
    const int EBLK = (ETOT + 255) / 256;             // 3321
    const int WGRD = (NN * 32 + 255) / 256;          // 6250 (warp per node)

    // ---------- conversions (weights + x) + deg zero ----------
    conv_all<<<384 + (NN * 32 + 255) / 256, 256>>>(
        lin_w0, skip_w0, lin_w1, skip_w1, lin_w2, skip_w2, x,
        wbhi, wblo, ahi, alo, deg);

    // ---------- CSR build (once, shared by all 3 layers) ----------
    k_count<<<EBLK, 256>>>(ei, deg);
    k_scan1<<<NB_SCAN, 256>>>(deg, ex, bsum);
    k_scan23<<<NB_SCAN, 256>>>(ex, bsum, rowptr, cursor);
    k_fill<<<EBLK, 256>>>(ei, cursor, csr);

    // ---------- layer 0 ----------
    gemm_dual_128<<<GB, 512, SM_TOTAL>>>(ahi, alo, wbhi, wblo,
                                         att_src0, att_dst0, xh_h, skipb, asrc, adst);
    gat_agg_128<<<WGRD, 256>>>(rowptr, csr, asrc, adst, xh_h, skipb, bias0, skip_b0, ahi, alo);

    // ---------- layer 1 ----------
    gemm_dual_128<<<GB, 512, SM_TOTAL>>>(ahi, alo, wbhi + 256 * 136, wblo + 256 * 136,
                                         att_src1, att_dst1, xh_h, skipb, asrc, adst);
    gat_agg_128<<<WGRD, 256>>>(rowptr, csr, asrc, adst, xh_h, skipb, bias1, skip_b1, ahi, alo);

    // ---------- layer 2 ----------
    gemm_l2<<<GB, 512, SM_TOTAL>>>(ahi, alo, wbhi + 512 * 136, wblo + 512 * 136,
                                   att_src2, att_dst2, xh_h, skipb, asrc, adst);
    gat_agg_188<<<WGRD, 256>>>(rowptr, csr, asrc, adst, xh_h, skipb, bias2, skip_b2, out);
}

// round 13
// speedup vs baseline: 3.0965x; 1.0314x over previous
#include <cuda_runtime.h>
#include <cuda_bf16.h>
#include <cuda_fp16.h>
#include <math.h>
#include <stdint.h>

#define NN 50000
#define EE 800000
#define ETOT (EE + NN)
#define NB_SCAN 196   // ceil(50000/256)

// ---------------- scratch (no allocations allowed) ----------------
__device__ __align__(16) __half         g_xh_h[NN * 188];   // lin output, fp16
__device__ __align__(16) float          g_skip[NN * 128];   // skip GEMM output (fp32)
__device__ __align__(16) __nv_bfloat16  g_ahi [NN * 128];   // A image hi
__device__ __align__(16) __nv_bfloat16  g_alo [NN * 128];   // A image lo
__device__ __align__(16) __nv_bfloat16  g_wbhi[768 * 136];  // weight images (3 layers)
__device__ __align__(16) __nv_bfloat16  g_wblo[768 * 136];
__device__ float    g_asrc[NN * 4];
__device__ float    g_adst[NN * 4];
// CSR scratch
__device__ int      g_deg   [NN];
__device__ int      g_ex    [NN];
__device__ int      g_bsum  [256];
__device__ int      g_rowptr[NN + 1];
__device__ int      g_cursor[NN];
__device__ int      g_csr   [ETOT];

// ---------------- helpers ----------------
__device__ __forceinline__ float lrelu(float e) { return fmaxf(e, 0.2f * e); }

__device__ __forceinline__ uint32_t smem_u32(const void* p) {
    uint32_t a;
    asm("{ .reg .u64 t; cvta.to.shared.u64 t, %1; cvt.u32.u64 %0, t; }"
        : "=r"(a) : "l"(p));
    return a;
}

__device__ __forceinline__ void split_bf16(float v, __nv_bfloat16& h, __nv_bfloat16& l) {
    h = __float2bfloat16_rn(v);
    l = __float2bfloat16_rn(v - __bfloat162float(h));
}

__device__ __forceinline__ uint32_t pack_bf16(__nv_bfloat16 a, __nv_bfloat16 b) {
    return (uint32_t)__bfloat16_as_ushort(a) |
           ((uint32_t)__bfloat16_as_ushort(b) << 16);
}

__device__ __forceinline__ void ldsm_x4(uint32_t& r0, uint32_t& r1,
                                        uint32_t& r2, uint32_t& r3, uint32_t addr) {
    asm volatile("ldmatrix.sync.aligned.m8n8.x4.shared.b16 {%0,%1,%2,%3}, [%4];"
                 : "=r"(r0), "=r"(r1), "=r"(r2), "=r"(r3) : "r"(addr));
}

__device__ __forceinline__ void mma_bf16(float* c, const uint32_t* a, const uint32_t* b) {
    asm volatile(
        "mma.sync.aligned.m16n8k16.row.col.f32.bf16.bf16.f32 "
        "{%0,%1,%2,%3}, {%4,%5,%6,%7}, {%8,%9}, {%0,%1,%2,%3};"
        : "+f"(c[0]), "+f"(c[1]), "+f"(c[2]), "+f"(c[3])
        : "r"(a[0]), "r"(a[1]), "r"(a[2]), "r"(a[3]), "r"(b[0]), "r"(b[1]));
}

// SMEM layout (bytes), stride 136 bf16 = 272B per row
#define AST       136
#define BST       136
#define SM_AHI    0
#define SM_ALO    (128 * AST * 2)                 // 34816
#define SM_BHI    (SM_ALO + 128 * AST * 2)        // 69632
#define SM_BLO    (SM_BHI + 256 * BST * 2)        // 139264
#define SM_TOTAL  (SM_BLO + 256 * BST * 2)        // 208896

// ================= merged conversion kernel =================
__global__ void conv_all(
    const float* __restrict__ w0l, const float* __restrict__ w0s,
    const float* __restrict__ w1l, const float* __restrict__ w1s,
    const float* __restrict__ w2l, const float* __restrict__ w2s,
    const float* __restrict__ X,
    __nv_bfloat16* __restrict__ whi, __nv_bfloat16* __restrict__ wlo,
    __nv_bfloat16* __restrict__ ahi, __nv_bfloat16* __restrict__ alo)
{
    int bx = blockIdx.x;
    if (bx < 384) {
        int idx = bx * 256 + threadIdx.x;          // over 768*128
        int n = idx >> 7, k = idx & 127;
        int layer = n >> 8, nl = n & 255;
        float v = 0.f;
        if (layer == 0) {
            v = (nl < 128) ? w0l[k * 128 + nl] : w0s[k * 128 + (nl - 128)];
        } else if (layer == 1) {
            v = (nl < 128) ? w1l[k * 128 + nl] : w1s[k * 128 + (nl - 128)];
        } else {
            if (nl < 188) v = w2l[k * 188 + nl];
            else if (nl >= 192 && nl < 239) v = w2s[k * 47 + (nl - 192)];
        }
        __nv_bfloat16 h, l;
        split_bf16(v, h, l);
        whi[n * 136 + k] = h;
        wlo[n * 136 + k] = l;
    } else {
        int idx = (bx - 384) * 256 + threadIdx.x;  // over NN*32 float4s
        if (idx >= NN * 32) return;
        float4 v = *(const float4*)(X + (long long)idx * 4);
        __nv_bfloat16 h0, l0, h1, l1, h2, l2, h3, l3;
        split_bf16(v.x, h0, l0); split_bf16(v.y, h1, l1);
        split_bf16(v.z, h2, l2); split_bf16(v.w, h3, l3);
        uint2 ph, pl;
        ph.x = pack_bf16(h0, h1); ph.y = pack_bf16(h2, h3);
        pl.x = pack_bf16(l0, l1); pl.y = pack_bf16(l2, l3);
        *(uint2*)((char*)ahi + (long long)idx * 8) = ph;
        *(uint2*)((char*)alo + (long long)idx * 8) = pl;
    }
}

// ================= CSR build =================
__global__ void k_count(const int* __restrict__ ei, int* __restrict__ deg) {
    int i = blockIdx.x * blockDim.x + threadIdx.x;
    if (i >= ETOT) return;
    int d = (i < EE) ? ei[EE + i] : i - EE;
    atomicAdd(&deg[d], 1);
}
__global__ void k_scan1(const int* __restrict__ deg, int* __restrict__ ex,
                        int* __restrict__ bsum) {
    __shared__ int sh[256];
    int t = threadIdx.x;
    int i = blockIdx.x * 256 + t;
    int v = (i < NN) ? deg[i] : 0;
    sh[t] = v;
    __syncthreads();
    for (int off = 1; off < 256; off <<= 1) {
        int a = (t >= off) ? sh[t - off] : 0;
        __syncthreads();
        sh[t] += a;
        __syncthreads();
    }
    if (i < NN) ex[i] = sh[t] - v;
    if (t == 255) bsum[blockIdx.x] = sh[255];
}
__global__ void k_scan23(const int* __restrict__ ex, const int* __restrict__ bsum,
                         int* __restrict__ rowptr, int* __restrict__ cursor) {
    __shared__ int sh[256];
    int t = threadIdx.x, b = blockIdx.x;
    sh[t] = (t < b) ? bsum[t] : 0;     // b <= 195 < 256
    __syncthreads();
    for (int off = 128; off; off >>= 1) {
        if (t < off) sh[t] += sh[t + off];
        __syncthreads();
    }
    int bpre = sh[0];
    int i = b * 256 + t;
    if (i < NN) {
        int r = ex[i] + bpre;
        rowptr[i] = r;
        cursor[i] = r;
    }
    if (i == 0) rowptr[NN] = ETOT;
}
__global__ void k_fill(const int* __restrict__ ei, int* __restrict__ cursor,
                       int* __restrict__ csr) {
    int i = blockIdx.x * blockDim.x + threadIdx.x;
    if (i >= ETOT) return;
    int s, d;
    if (i < EE) { s = ei[i]; d = ei[EE + i]; } else { s = d = i - EE; }
    int pos = atomicAdd(&cursor[d], 1);
    csr[pos] = s;
}

// ============ staging (pure copies) + mma mainloop ============
__device__ __forceinline__ void stage_A2(char* sm, const __nv_bfloat16* __restrict__ ahi,
                                         const __nv_bfloat16* __restrict__ alo,
                                         int row0, int tid) {
    #pragma unroll
    for (int jj = 0; jj < 4; jj++) {
        int i = tid + jj * 512;          // 0..2047
        int r = i >> 4, q = i & 15;      // row, uint4 idx (16B)
        uint4 vh = make_uint4(0, 0, 0, 0), vl = make_uint4(0, 0, 0, 0);
        if (row0 + r < NN) {
            long long bofs = ((long long)(row0 + r) * 128 + q * 8) * 2;
            vh = *(const uint4*)((const char*)ahi + bofs);
            vl = *(const uint4*)((const char*)alo + bofs);
        }
        *(uint4*)(sm + SM_AHI + r * (AST * 2) + q * 16) = vh;
        *(uint4*)(sm + SM_ALO + r * (AST * 2) + q * 16) = vl;
    }
}

__device__ __forceinline__ void stage_B2(char* sm, const __nv_bfloat16* __restrict__ whi,
                                         const __nv_bfloat16* __restrict__ wlo, int tid) {
    #pragma unroll
    for (int jj = 0; jj < 9; jj++) {
        int i = tid + jj * 512;
        if (i < 4352) {
            *(uint4*)(sm + SM_BHI + i * 16) = *(const uint4*)((const char*)whi + i * 16);
            *(uint4*)(sm + SM_BLO + i * 16) = *(const uint4*)((const char*)wlo + i * 16);
        }
    }
}

__device__ __forceinline__ void mma_mainloop(char* sm, float acc[2][8][4],
                                             int wid, int lane) {
    const uint32_t sb = smem_u32(sm);
    const int wm = wid >> 2, wn = wid & 3;
    const int m0r = wm * 32, n0 = wn * 64;
    const int ar = (lane & 15), ak = (lane >> 4) * 8;
    const int bn = ((lane >> 4) * 8) + (lane & 7);
    const int bk = ((lane >> 3) & 1) * 8;

    #pragma unroll
    for (int ks = 0; ks < 8; ks++) {
        int k0 = ks * 16;
        uint32_t ahi[2][4], alo[2][4], bhi[8][2], blo[8][2];
        #pragma unroll
        for (int mt = 0; mt < 2; mt++) {
            uint32_t addr = sb + SM_AHI + (m0r + mt * 16 + ar) * (AST * 2) + (k0 + ak) * 2;
            ldsm_x4(ahi[mt][0], ahi[mt][1], ahi[mt][2], ahi[mt][3], addr);
        }
        #pragma unroll
        for (int p = 0; p < 4; p++) {
            uint32_t addr = sb + SM_BHI + (n0 + p * 16 + bn) * (BST * 2) + (k0 + bk) * 2;
            ldsm_x4(bhi[2 * p][0], bhi[2 * p][1], bhi[2 * p + 1][0], bhi[2 * p + 1][1], addr);
        }
        #pragma unroll
        for (int mt = 0; mt < 2; mt++)
            #pragma unroll
            for (int nt = 0; nt < 8; nt++)
                mma_bf16(acc[mt][nt], ahi[mt], bhi[nt]);
        #pragma unroll
        for (int p = 0; p < 4; p++) {
            uint32_t addr = sb + SM_BLO + (n0 + p * 16 + bn) * (BST * 2) + (k0 + bk) * 2;
            ldsm_x4(blo[2 * p][0], blo[2 * p][1], blo[2 * p + 1][0], blo[2 * p + 1][1], addr);
        }
        #pragma unroll
        for (int mt = 0; mt < 2; mt++)
            #pragma unroll
            for (int nt = 0; nt < 8; nt++)
                mma_bf16(acc[mt][nt], ahi[mt], blo[nt]);
        #pragma unroll
        for (int mt = 0; mt < 2; mt++) {
            uint32_t addr = sb + SM_ALO + (m0r + mt * 16 + ar) * (AST * 2) + (k0 + ak) * 2;
            ldsm_x4(alo[mt][0], alo[mt][1], alo[mt][2], alo[mt][3], addr);
        }
        #pragma unroll
        for (int mt = 0; mt < 2; mt++)
            #pragma unroll
            for (int nt = 0; nt < 8; nt++)
                mma_bf16(acc[mt][nt], alo[mt], bhi[nt]);
    }
}

// ================= dual GEMM, layers 0/1 + fused attention scores =========
__global__ __launch_bounds__(512, 1) void gemm_dual_128(
    const __nv_bfloat16* __restrict__ ahi, const __nv_bfloat16* __restrict__ alo,
    const __nv_bfloat16* __restrict__ whi, const __nv_bfloat16* __restrict__ wlo,
    const float* __restrict__ AttS, const float* __restrict__ AttD,
    __half* __restrict__ Xh, float* __restrict__ Oskip,
    float* __restrict__ asrc, float* __restrict__ adst)
{
    extern __shared__ char sm[];
    const int tid = threadIdx.x;
    const int wid = tid >> 5, lane = tid & 31;
    const int row0 = blockIdx.x << 7;

    stage_A2(sm, ahi, alo, row0, tid);
    stage_B2(sm, whi, wlo, tid);
    __syncthreads();

    float acc[2][8][4];
    #pragma unroll
    for (int i = 0; i < 2; i++)
        #pragma unroll
        for (int j = 0; j < 8; j++)
            #pragma unroll
            for (int q = 0; q < 4; q++) acc[i][j][q] = 0.f;

    mma_mainloop(sm, acc, wid, lane);

    const int wm = wid >> 2, wn = wid & 3;
    const int g = lane >> 2, t = lane & 3;

    #pragma unroll
    for (int mt = 0; mt < 2; mt++) {
        #pragma unroll
        for (int half_ = 0; half_ < 2; half_++) {
            int row = row0 + wm * 32 + mt * 16 + g + half_ * 8;
            if (row >= NN) continue;
            #pragma unroll
            for (int nt = 0; nt < 8; nt++) {
                int c = wn * 64 + nt * 8 + t * 2;
                float2 v = make_float2(acc[mt][nt][half_ * 2 + 0],
                                       acc[mt][nt][half_ * 2 + 1]);
                if (c < 128)
                    *(__half2*)(Xh + (long long)row * 128 + c) = __float22half2_rn(v);
                else
                    *(float2*)(Oskip + (long long)row * 128 + (c - 128)) = v;
            }
        }
    }

    if (wn < 2) {
        #pragma unroll
        for (int mt = 0; mt < 2; mt++) {
            #pragma unroll
            for (int half_ = 0; half_ < 2; half_++) {
                float ps0 = 0.f, ps1 = 0.f, pd0 = 0.f, pd1 = 0.f;
                #pragma unroll
                for (int nt = 0; nt < 8; nt++) {
                    #pragma unroll
                    for (int q = 0; q < 2; q++) {
                        int c = wn * 64 + nt * 8 + t * 2 + q;
                        float v = acc[mt][nt][half_ * 2 + q];
                        float cs = AttS[c], cd = AttD[c];
                        if (nt < 4) { ps0 += v * cs; pd0 += v * cd; }
                        else        { ps1 += v * cs; pd1 += v * cd; }
                    }
                }
                ps0 += __shfl_xor_sync(0xFFFFFFFFu, ps0, 1);
                ps0 += __shfl_xor_sync(0xFFFFFFFFu, ps0, 2);
                ps1 += __shfl_xor_sync(0xFFFFFFFFu, ps1, 1);
                ps1 += __shfl_xor_sync(0xFFFFFFFFu, ps1, 2);
                pd0 += __shfl_xor_sync(0xFFFFFFFFu, pd0, 1);
                pd0 += __shfl_xor_sync(0xFFFFFFFFu, pd0, 2);
                pd1 += __shfl_xor_sync(0xFFFFFFFFu, pd1, 1);
                pd1 += __shfl_xor_sync(0xFFFFFFFFu, pd1, 2);
                int row = row0 + wm * 32 + mt * 16 + g + half_ * 8;
                if (t == 0 && row < NN) {
                    int h0 = wn * 2, h1 = wn * 2 + 1;
                    asrc[row * 4 + h0] = ps0;
                    asrc[row * 4 + h1] = ps1;
                    adst[row * 4 + h0] = pd0;
                    adst[row * 4 + h1] = pd1;
                }
            }
        }
    }
}

// ================= layer-2 GEMM + fused attention scores ==================
__global__ __launch_bounds__(512, 1) void gemm_l2(
    const __nv_bfloat16* __restrict__ ahi, const __nv_bfloat16* __restrict__ alo,
    const __nv_bfloat16* __restrict__ whi, const __nv_bfloat16* __restrict__ wlo,
    const float* __restrict__ AttS, const float* __restrict__ AttD,
    __half* __restrict__ Xh, float* __restrict__ Oskip,
    float* __restrict__ asrc, float* __restrict__ adst)
{
    extern __shared__ char sm[];
    const int tid = threadIdx.x;
    const int wid = tid >> 5, lane = tid & 31;
    const int row0 = blockIdx.x << 7;

    stage_A2(sm, ahi, alo, row0, tid);
    stage_B2(sm, whi, wlo, tid);
    __syncthreads();

    float acc[2][8][4];
    #pragma unroll
    for (int i = 0; i < 2; i++)
        #pragma unroll
        for (int j = 0; j < 8; j++)
            #pragma unroll
            for (int q = 0; q < 4; q++) acc[i][j][q] = 0.f;

    mma_mainloop(sm, acc, wid, lane);

    const int wm = wid >> 2, wn = wid & 3;
    const int g = lane >> 2, t = lane & 3;
    #pragma unroll
    for (int mt = 0; mt < 2; mt++) {
        #pragma unroll
        for (int half_ = 0; half_ < 2; half_++) {
            int row = row0 + wm * 32 + mt * 16 + g + half_ * 8;
            if (row >= NN) continue;
            #pragma unroll
            for (int nt = 0; nt < 8; nt++) {
                int c = wn * 64 + nt * 8 + t * 2;
                float2 v = make_float2(acc[mt][nt][half_ * 2 + 0],
                                       acc[mt][nt][half_ * 2 + 1]);
                if (c < 188) {
                    *(__half2*)(Xh + (long long)row * 188 + c) = __float22half2_rn(v);
                } else {
                    #pragma unroll
                    for (int q = 0; q < 2; q++) {
                        int cc = c + q;
                        if (cc >= 192 && cc < 239)
                            Oskip[(long long)row * 47 + (cc - 192)] = (q ? v.y : v.x);
                    }
                }
            }
        }
    }

    // ---- fused layer-2 attention scores (head = c/47) ----
    __syncthreads();
    float* satt = (float*)sm;
    for (int i = tid; i < 128 * 8; i += 512) satt[i] = 0.f;
    __syncthreads();

    #pragma unroll
    for (int mt = 0; mt < 2; mt++) {
        #pragma unroll
        for (int half_ = 0; half_ < 2; half_++) {
            float ps[4] = {0.f, 0.f, 0.f, 0.f}, pd[4] = {0.f, 0.f, 0.f, 0.f};
            #pragma unroll
            for (int nt = 0; nt < 8; nt++) {
                #pragma unroll
                for (int q = 0; q < 2; q++) {
                    int c = wn * 64 + nt * 8 + t * 2 + q;
                    if (c < 188) {
                        float v = acc[mt][nt][half_ * 2 + q];
                        int h = c / 47;
                        ps[h] += v * AttS[c];
                        pd[h] += v * AttD[c];
                    }
                }
            }
            #pragma unroll
            for (int h = 0; h < 4; h++) {
                ps[h] += __shfl_xor_sync(0xFFFFFFFFu, ps[h], 1);
                ps[h] += __shfl_xor_sync(0xFFFFFFFFu, ps[h], 2);
                pd[h] += __shfl_xor_sync(0xFFFFFFFFu, pd[h], 1);
                pd[h] += __shfl_xor_sync(0xFFFFFFFFu, pd[h], 2);
            }
            if (t == 0) {
                int rloc = wm * 32 + mt * 16 + g + half_ * 8;
                #pragma unroll
                for (int h = 0; h < 4; h++) {
                    atomicAdd(&satt[rloc * 8 + h * 2 + 0], ps[h]);
                    atomicAdd(&satt[rloc * 8 + h * 2 + 1], pd[h]);
                }
            }
        }
    }
    __syncthreads();
    for (int i = tid; i < 128 * 4; i += 512) {
        int rloc = i >> 2, h = i & 3;
        int row = row0 + rloc;
        if (row < NN) {
            asrc[row * 4 + h] = satt[rloc * 8 + h * 2 + 0];
            adst[row * 4 + h] = satt[rloc * 8 + h * 2 + 1];
        }
    }
}

// ================= fused GAT aggregation (F=128), single-pass =============
__global__ __launch_bounds__(256) void gat_agg_128(
    const int* __restrict__ rowptr, const int* __restrict__ csr,
    const float* __restrict__ asrc, const float* __restrict__ adst,
    const __half* __restrict__ xh, const float* __restrict__ skipb,
    const float* __restrict__ bias, const float* __restrict__ skip_b,
    __nv_bfloat16* __restrict__ ahi, __nv_bfloat16* __restrict__ alo)
{
    int w = (blockIdx.x * blockDim.x + threadIdx.x) >> 5;
    if (w >= NN) return;
    int lane = threadIdx.x & 31;
    int h = lane >> 3;
    int beg = rowptr[w], end = rowptr[w + 1];
    float adh = adst[4 * w + h];

    float sh = 0.f;
    float4 acc = make_float4(0.f, 0.f, 0.f, 0.f);
    #pragma unroll 4
    for (int e = beg; e < end; e++) {
        int s = csr[e];
        float as = asrc[4 * s + h];
        float wl = __expf(lrelu(as + adh));
        sh += wl;
        uint2 raw = *(const uint2*)(xh + (long long)s * 128 + lane * 4);
        float2 p0 = __half22float2(*(const __half2*)&raw.x);
        float2 p1 = __half22float2(*(const __half2*)&raw.y);
        acc.x += wl * p0.x; acc.y += wl * p0.y;
        acc.z += wl * p1.x; acc.w += wl * p1.y;
    }
    float inv = 1.f / (sh + 1e-16f);

    int base = w * 128 + lane * 4;
    float4 sk = *(const float4*)(skipb + base);
    float4 bi = *(const float4*)(bias + lane * 4);
    float4 sb = *(const float4*)(skip_b + lane * 4);
    float4 o;
    o.x = acc.x * inv + sk.x + bi.x + sb.x;
    o.y = acc.y * inv + sk.y + bi.y + sb.y;
    o.z = acc.z * inv + sk.z + bi.z + sb.z;
    o.w = acc.w * inv + sk.w + bi.w + sb.w;
    o.x = o.x > 0.f ? o.x : expm1f(o.x);
    o.y = o.y > 0.f ? o.y : expm1f(o.y);
    o.z = o.z > 0.f ? o.z : expm1f(o.z);
    o.w = o.w > 0.f ? o.w : expm1f(o.w);

    __nv_bfloat16 h0, l0, h1, l1, h2, l2, h3, l3;
    split_bf16(o.x, h0, l0); split_bf16(o.y, h1, l1);
    split_bf16(o.z, h2, l2); split_bf16(o.w, h3, l3);
    uint2 ph, pl;
    ph.x = pack_bf16(h0, h1); ph.y = pack_bf16(h2, h3);
    pl.x = pack_bf16(l0, l1); pl.y = pack_bf16(l2, l3);
    *(uint2*)((char*)ahi + (long long)base * 2) = ph;
    *(uint2*)((char*)alo + (long long)base * 2) = pl;
}

// ================= fused GAT aggregation (layer 2, head-mean) =============
__global__ __launch_bounds__(256) void gat_agg_188(
    const int* __restrict__ rowptr, const int* __restrict__ csr,
    const float* __restrict__ asrc, const float* __restrict__ adst,
    const __half* __restrict__ xh, const float* __restrict__ skipb,
    const float* __restrict__ bias2, const float* __restrict__ skip_b2,
    float* __restrict__ out)
{
    int w = (blockIdx.x * blockDim.x + threadIdx.x) >> 5;
    if (w >= NN) return;
    int lane = threadIdx.x & 31;
    int beg = rowptr[w], end = rowptr[w + 1];
    float4 ad = *(const float4*)(adst + 4 * w);

    float4 s4 = make_float4(0.f, 0.f, 0.f, 0.f);
    float a00 = 0.f, a01 = 0.f, a02 = 0.f, a03 = 0.f;
    float a10 = 0.f, a11 = 0.f, a12 = 0.f, a13 = 0.f;
    int o1 = lane + 32;
    #pragma unroll 2
    for (int e = beg; e < end; e++) {
        int s = csr[e];
        float4 a = *(const float4*)(asrc + 4 * s);
        float wx = __expf(lrelu(a.x + ad.x));
        float wy = __expf(lrelu(a.y + ad.y));
        float wz = __expf(lrelu(a.z + ad.z));
        float ww = __expf(lrelu(a.w + ad.w));
        s4.x += wx; s4.y += wy; s4.z += wz; s4.w += ww;
        const __half* row = xh + (long long)s * 188;
        a00 += wx * __half2float(row[lane]);
        a01 += wy * __half2float(row[47 + lane]);
        a02 += wz * __half2float(row[94 + lane]);
        a03 += ww * __half2float(row[141 + lane]);
        if (o1 < 47) {
            a10 += wx * __half2float(row[o1]);
            a11 += wy * __half2float(row[47 + o1]);
            a12 += wz * __half2float(row[94 + o1]);
            a13 += ww * __half2float(row[141 + o1]);
        }
    }
    float ix = 1.f / (s4.x + 1e-16f);
    float iy = 1.f / (s4.y + 1e-16f);
    float iz = 1.f / (s4.z + 1e-16f);
    float iw = 1.f / (s4.w + 1e-16f);

    {
        int o = lane;
        float v = 0.25f * (a00 * ix + a01 * iy + a02 * iz + a03 * iw);
        out[w * 47 + o] = v + bias2[o] + skipb[w * 47 + o] + skip_b2[o];
    }
    if (o1 < 47) {
        float v = 0.25f * (a10 * ix + a11 * iy + a12 * iz + a13 * iw);
        out[w * 47 + o1] = v + bias2[o1] + skipb[w * 47 + o1] + skip_b2[o1];
    }
}

// ---------------- launch ----------------
extern "C" void kernel_launch(void* const* d_in, const int* in_sizes, int n_in,
                              void* d_out, int out_size)
{
    const float* x        = (const float*)d_in[0];
    const int*   ei       = (const int*)  d_in[1];
    const float* lin_w0   = (const float*)d_in[2];
    const float* att_src0 = (const float*)d_in[3];
    const float* att_dst0 = (const float*)d_in[4];
    const float* bias0    = (const float*)d_in[5];
    const float* skip_w0  = (const float*)d_in[6];
    const float* skip_b0  = (const float*)d_in[7];
    const float* lin_w1   = (const float*)d_in[8];
    const float* att_src1 = (const float*)d_in[9];
    const float* att_dst1 = (const float*)d_in[10];
    const float* bias1    = (const float*)d_in[11];
    const float* skip_w1  = (const float*)d_in[12];
    const float* skip_b1  = (const float*)d_in[13];
    const float* lin_w2   = (const float*)d_in[14];
    const float* att_src2 = (const float*)d_in[15];
    const float* att_dst2 = (const float*)d_in[16];
    const float* bias2    = (const float*)d_in[17];
    const float* skip_w2  = (const float*)d_in[18];
    const float* skip_b2  = (const float*)d_in[19];
    float* out = (float*)d_out;

    __half* xh_h; float *skipb, *asrc, *adst;
    __nv_bfloat16 *ahi, *alo, *wbhi, *wblo;
    int *deg, *ex, *bsum, *rowptr, *cursor, *csr;
    cudaGetSymbolAddress((void**)&xh_h,   g_xh_h);
    cudaGetSymbolAddress((void**)&skipb,  g_skip);
    cudaGetSymbolAddress((void**)&ahi,    g_ahi);
    cudaGetSymbolAddress((void**)&alo,    g_alo);
    cudaGetSymbolAddress((void**)&wbhi,   g_wbhi);
    cudaGetSymbolAddress((void**)&wblo,   g_wblo);
    cudaGetSymbolAddress((void**)&asrc,   g_asrc);
    cudaGetSymbolAddress((void**)&adst,   g_adst);
    cudaGetSymbolAddress((void**)&deg,    g_deg);
    cudaGetSymbolAddress((void**)&ex,     g_ex);
    cudaGetSymbolAddress((void**)&bsum,   g_bsum);
    cudaGetSymbolAddress((void**)&rowptr, g_rowptr);
    cudaGetSymbolAddress((void**)&cursor, g_cursor);
    cudaGetSymbolAddress((void**)&csr,    g_csr);

    static cudaStream_t s1 = nullptr;
    static cudaEvent_t ev_fork = nullptr, ev_join = nullptr;
    static int once = 0;
    if (!once) {
        cudaFuncSetAttribute(gemm_dual_128, cudaFuncAttributeMaxDynamicSharedMemorySize, SM_TOTAL);
        cudaFuncSetAttribute(gemm_l2,       cudaFuncAttributeMaxDynamicSharedMemorySize, SM_TOTAL);
        cudaStreamCreateWithFlags(&s1, cudaStreamNonBlocking);
        cudaEventCreateWithFlags(&ev_fork, cudaEventDisableTiming);
        cudaEventCreateWithFlags(&ev_join, cudaEventDisableTiming);
        once = 1;
    }

    const int GB   = (NN + 127) / 128;               // 391 GEMM row blocks
    const int EBLK = (ETOT + 255) / 256;             // 3321
    const int WGRD = (NN * 32 + 255) / 256;          // 6250 (warp per node)

    // ---------- fork: CSR build on side stream, concurrent with conv+gemm0 --
    cudaEventRecord(ev_fork, 0);
    cudaStreamWaitEvent(s1, ev_fork, 0);
    cudaMemsetAsync(deg, 0, NN * sizeof(int), s1);
    k_count<<<EBLK, 256, 0, s1>>>(ei, deg);
    k_scan1<<<NB_SCAN, 256, 0, s1>>>(deg, ex, bsum);
    k_scan23<<<NB_SCAN, 256, 0, s1>>>(ex, bsum, rowptr, cursor);
    k_fill<<<EBLK, 256, 0, s1>>>(ei, cursor, csr);
    cudaEventRecord(ev_join, s1);

    // ---------- main stream: conversions + layer-0 GEMM ----------
    conv_all<<<384 + (NN * 32 + 255) / 256, 256>>>(
        lin_w0, skip_w0, lin_w1, skip_w1, lin_w2, skip_w2, x,
        wbhi, wblo, ahi, alo);
    gemm_dual_128<<<GB, 512, SM_TOTAL>>>(ahi, alo, wbhi, wblo,
                                         att_src0, att_dst0, xh_h, skipb, asrc, adst);

    // join: aggregation needs the CSR
    cudaStreamWaitEvent(0, ev_join, 0);

    // ---------- layer 0 ----------
    gat_agg_128<<<WGRD, 256>>>(rowptr, csr, asrc, adst, xh_h, skipb, bias0, skip_b0, ahi, alo);

    // ---------- layer 1 ----------
    gemm_dual_128<<<GB, 512, SM_TOTAL>>>(ahi, alo, wbhi + 256 * 136, wblo + 256 * 136,
                                         att_src1, att_dst1, xh_h, skipb, asrc, adst);
    gat_agg_128<<<WGRD, 256>>>(rowptr, csr, asrc, adst, xh_h, skipb, bias1, skip_b1, ahi, alo);

    // ---------- layer 2 ----------
    gemm_l2<<<GB, 512, SM_TOTAL>>>(ahi, alo, wbhi + 512 * 136, wblo + 512 * 136,
                                   att_src2, att_dst2, xh_h, skipb, asrc, adst);
    gat_agg_188<<<WGRD, 256>>>(rowptr, csr, asrc, adst, xh_h, skipb, bias2, skip_b2, out);
}